// round 2
// baseline (speedup 1.0000x reference)
#include <cuda_runtime.h>
#include <cstddef>

// MultiDecoder: A=10 independent MLPs 12 -> 128 -> 256 -> 200 over 32768 tokens.
// Fused single kernel: block = (64-token tile, articulator).
// Phase A: h1 = relu(x_g @ W1 + b1)     (tiny)
// Phase B: h2 = relu(h1 @ W2 + b2)      (64x256x128 GEMM, reg-tiled 4x16)
// Phase C: out = h2 @ W3 + b3           (64x208x256 GEMM, reg-tiled 4x13, cols padded)
// Intermediates kept transposed [k][token] in smem for float4 A-loads.
// Output staged through smem for coalesced global stores.

#define NA   10
#define NC   12
#define NH2  128
#define NH   256
#define NF   200
#define NFP  208      // padded col count for phase C (16 groups x 13)
#define NL   120
#define NTOK 32768
#define TM   64       // tokens per block
#define NTHREADS 256
#define KT   32       // k-chunk staged in smem

// dynamic smem layout (floats):
//   s_h1 [NH2][TM]   = 8192      offset 0
//   s_h2 [NH][TM]    = 16384     offset 8192   (reused as s_out[TM][NF]=12800)
//   s_w  [KT][NH]    = 8192      offset 24576  (phase C uses [KT][NFP]=6656)
//   s_x  [TM][NC]    = 768       offset 32768
#define SMEM_FLOATS (NH2*TM + NH*TM + KT*NH + TM*NC)
#define SMEM_BYTES  (SMEM_FLOATS * (int)sizeof(float))

__global__ void __launch_bounds__(NTHREADS, 1)
multidecoder_kernel(const float* __restrict__ x,
                    const float* __restrict__ W1, const float* __restrict__ b1,
                    const float* __restrict__ W2, const float* __restrict__ b2,
                    const float* __restrict__ W3, const float* __restrict__ b3,
                    const int*   __restrict__ idx,
                    float* __restrict__ out)
{
    extern __shared__ float smem[];
    float* s_h1 = smem;                      // [NH2][TM]
    float* s_h2 = smem + NH2 * TM;           // [NH][TM]
    float* s_w  = smem + NH2 * TM + NH * TM; // [KT][NH] / [KT][NFP]
    float* s_x  = s_w + KT * NH;             // [TM][NC]

    const int a   = blockIdx.y;
    const int n0  = blockIdx.x * TM;
    const int tid = threadIdx.x;

    // ---------------- load gathered x tile ----------------
    for (int i = tid; i < TM * NC; i += NTHREADS) {
        int t = i / NC, c = i % NC;
        s_x[i] = x[(size_t)(n0 + t) * NL + idx[a * NC + c]];
    }
    __syncthreads();

    // ---------------- phase A: layer 1 (12 -> 128) ----------------
    {
        const float* W1a = W1 + a * NC * NH2;
        const float* b1a = b1 + a * NH2;
        const int t  = tid & (TM - 1);
        const int hg = tid >> 6;             // 0..3, 32 h-values each
        float xv[NC];
        #pragma unroll
        for (int c = 0; c < NC; c++) xv[c] = s_x[t * NC + c];
        #pragma unroll 4
        for (int j = 0; j < 32; j++) {
            const int h = hg * 32 + j;
            float acc = b1a[h];
            #pragma unroll
            for (int c = 0; c < NC; c++)
                acc = fmaf(xv[c], W1a[c * NH2 + h], acc);
            s_h1[h * TM + t] = fmaxf(acc, 0.0f);
        }
    }
    __syncthreads();

    // ---------------- phase B: layer 2 (128 -> 256) ----------------
    {
        const float* W2a = W2 + (size_t)a * NH2 * NH;
        const int tx = tid & 15;   // tokens 4*tx .. 4*tx+3
        const int ty = tid >> 4;   // cols  16*ty .. 16*ty+15
        float acc[4][16];
        #pragma unroll
        for (int tt = 0; tt < 4; tt++)
            #pragma unroll
            for (int jj = 0; jj < 16; jj++) acc[tt][jj] = 0.0f;

        for (int kc = 0; kc < NH2; kc += KT) {
            __syncthreads();  // previous s_w chunk fully consumed
            // stage W2[kc..kc+KT) rows, vectorized
            const float4* src = (const float4*)(W2a + (size_t)kc * NH);
            float4* dst = (float4*)s_w;
            for (int i = tid; i < KT * NH / 4; i += NTHREADS) dst[i] = src[i];
            __syncthreads();

            #pragma unroll 4
            for (int kk = 0; kk < KT; kk++) {
                float4 av = *(const float4*)(s_h1 + (kc + kk) * TM + 4 * tx);
                float ar[4] = {av.x, av.y, av.z, av.w};
                float br[16];
                #pragma unroll
                for (int m = 0; m < 4; m++) {
                    float4 bv = *(const float4*)(s_w + kk * NH + 16 * ty + 4 * m);
                    br[4 * m + 0] = bv.x; br[4 * m + 1] = bv.y;
                    br[4 * m + 2] = bv.z; br[4 * m + 3] = bv.w;
                }
                #pragma unroll
                for (int tt = 0; tt < 4; tt++)
                    #pragma unroll
                    for (int jj = 0; jj < 16; jj++)
                        acc[tt][jj] = fmaf(ar[tt], br[jj], acc[tt][jj]);
            }
        }
        __syncthreads();  // all reads of s_h1/s_w done before s_h2 write races next staging
        const float* b2a = b2 + a * NH;
        #pragma unroll
        for (int jj = 0; jj < 16; jj++) {
            const int j = 16 * ty + jj;
            const float bb = b2a[j];
            #pragma unroll
            for (int tt = 0; tt < 4; tt++)
                s_h2[j * TM + 4 * tx + tt] = fmaxf(acc[tt][jj] + bb, 0.0f);
        }
    }

    // ---------------- phase C: layer 3 (256 -> 200) ----------------
    {
        const float* W3a = W3 + (size_t)a * NH * NF;
        const int tx = tid & 15;   // tokens 4*tx .. 4*tx+3
        const int ty = tid >> 4;   // cols  13*ty .. 13*ty+12 (padded to 208)
        float acc[4][13];
        #pragma unroll
        for (int tt = 0; tt < 4; tt++)
            #pragma unroll
            for (int m = 0; m < 13; m++) acc[tt][m] = 0.0f;

        for (int kc = 0; kc < NH; kc += KT) {
            __syncthreads();  // also covers: s_h2 writes visible before first read
            // stage W3 chunk [KT][NFP], zero-padded cols >= NF
            for (int i = tid; i < KT * NFP; i += NTHREADS) {
                int kk = i / NFP, j = i % NFP;
                s_w[i] = (j < NF) ? W3a[(size_t)(kc + kk) * NF + j] : 0.0f;
            }
            __syncthreads();

            #pragma unroll 4
            for (int kk = 0; kk < KT; kk++) {
                float4 av = *(const float4*)(s_h2 + (kc + kk) * TM + 4 * tx);
                float ar[4] = {av.x, av.y, av.z, av.w};
                float br[13];
                #pragma unroll
                for (int m = 0; m < 13; m++) br[m] = s_w[kk * NFP + 13 * ty + m];
                #pragma unroll
                for (int tt = 0; tt < 4; tt++)
                    #pragma unroll
                    for (int m = 0; m < 13; m++)
                        acc[tt][m] = fmaf(ar[tt], br[m], acc[tt][m]);
            }
        }
        __syncthreads();               // all s_h2 reads done; reuse it as s_out
        float* s_out = s_h2;           // [TM][NF]
        const float* b3a = b3 + a * NF;
        #pragma unroll
        for (int m = 0; m < 13; m++) {
            const int j = 13 * ty + m;
            if (j < NF) {
                const float bb = b3a[j];
                #pragma unroll
                for (int tt = 0; tt < 4; tt++)
                    s_out[(4 * tx + tt) * NF + j] = acc[tt][m] + bb;
            }
        }
        __syncthreads();
        // coalesced global store: 64 tokens x 200 floats
        for (int i = tid; i < TM * NF; i += NTHREADS) {
            int t = i / NF, j = i % NF;
            out[((size_t)(n0 + t) * NA + a) * NF + j] = s_out[i];
        }
    }
}

extern "C" void kernel_launch(void* const* d_in, const int* in_sizes, int n_in,
                              void* d_out, int out_size)
{
    // Identify inputs by element count (all distinct) — robust to ordering.
    const float *x = nullptr, *W1 = nullptr, *b1 = nullptr, *W2 = nullptr,
                *b2 = nullptr, *W3 = nullptr, *b3 = nullptr;
    const int* idx = nullptr;
    for (int i = 0; i < n_in; i++) {
        switch (in_sizes[i]) {
            case NTOK * NL:       x   = (const float*)d_in[i]; break;   // 3932160
            case NA * NC * NH2:   W1  = (const float*)d_in[i]; break;   // 15360
            case NA * NH2:        b1  = (const float*)d_in[i]; break;   // 1280
            case NA * NH2 * NH:   W2  = (const float*)d_in[i]; break;   // 327680
            case NA * NH:         b2  = (const float*)d_in[i]; break;   // 2560
            case NA * NH * NF:    W3  = (const float*)d_in[i]; break;   // 512000
            case NA * NF:         b3  = (const float*)d_in[i]; break;   // 2000
            case NA * NC:         idx = (const int*)d_in[i];   break;   // 120
            default: break;
        }
    }

    cudaFuncSetAttribute(multidecoder_kernel,
                         cudaFuncAttributeMaxDynamicSharedMemorySize, SMEM_BYTES);

    dim3 grid(NTOK / TM, NA);
    multidecoder_kernel<<<grid, NTHREADS, SMEM_BYTES>>>(
        x, W1, b1, W2, b2, W3, b3, idx, (float*)d_out);
}

// round 4
// speedup vs baseline: 3.4225x; 3.4225x over previous
#include <cuda_runtime.h>
#include <cuda_bf16.h>
#include <cstdint>
#include <cstddef>

// MultiDecoder: A=10 MLPs 12->128->256->200 over 32768 tokens.
// fp32 scalar layer1 + bf16 two-term-split mma.sync (m16n8k16) layers 2 & 3.
// Base-target PTX only (mma.sync/ldmatrix/cp.async) -- no tcgen05 (harness
// compiles at compute_103 without the 'a' feature set).
// CTA = (articulator, 128 tokens), 8 warps = (m-half 64) x (4 n-groups).

#define NA 10
#define NC 12
#define NH2 128
#define NH 256
#define NF 200
#define NL 120
#define NTOK 32768
#define TM 128

#define LDA 264                 // A smem pitch (elems): 528B rows, conflict-free
#define LDB 40                  // B stage pitch (elems): 80B rows, conflict-free
#define APLANE 67584            // 128*264*2 bytes per term plane
#define BTERM 20480             // 256*40*2 bytes per term within a stage
#define BSTAGE 40960            // 2 terms
#define OFF_A 0                 // 2 planes = 135168
#define OFF_B 135168            // 2 stages = 81920
#define OFF_X (OFF_B + BSTAGE)          // s_x inside stage1 (dead before stage1 used)
#define OFF_W1 (OFF_X + TM * 13 * 4)
#define OFF_BIAS 217088         // b2[256] + b3[208] floats
#define SMEM_REQ (OFF_BIAS + (256 + 208) * 4)   // 218944 bytes

// weights pre-split (hi/lo bf16) and pre-transposed to [n][k]
__device__ __nv_bfloat16 g_w2t[2 * NA * 256 * 128];   // [term][a][n=256][k=128]
__device__ __nv_bfloat16 g_w3t[2 * NA * 200 * 256];   // [term][a][n=200][k=256]

// ---------------- PTX helpers (all base-target) ----------------
__device__ __forceinline__ void mma_bf16(float* c, const unsigned* a, const unsigned* b) {
    asm volatile("mma.sync.aligned.m16n8k16.row.col.f32.bf16.bf16.f32 "
                 "{%0,%1,%2,%3}, {%4,%5,%6,%7}, {%8,%9}, {%0,%1,%2,%3};"
                 : "+f"(c[0]), "+f"(c[1]), "+f"(c[2]), "+f"(c[3])
                 : "r"(a[0]), "r"(a[1]), "r"(a[2]), "r"(a[3]), "r"(b[0]), "r"(b[1]));
}
__device__ __forceinline__ void ldsm_x4(unsigned* r, uint32_t addr) {
    asm volatile("ldmatrix.sync.aligned.m8n8.x4.shared.b16 {%0,%1,%2,%3}, [%4];"
                 : "=r"(r[0]), "=r"(r[1]), "=r"(r[2]), "=r"(r[3]) : "r"(addr));
}
__device__ __forceinline__ void ldsm_x2(unsigned* r, uint32_t addr) {
    asm volatile("ldmatrix.sync.aligned.m8n8.x2.shared.b16 {%0,%1}, [%2];"
                 : "=r"(r[0]), "=r"(r[1]) : "r"(addr));
}
__device__ __forceinline__ void cpa16(uint32_t dst, const void* src) {
    asm volatile("cp.async.cg.shared.global [%0], [%1], 16;" ::"r"(dst), "l"(src) : "memory");
}
#define CP_COMMIT() asm volatile("cp.async.commit_group;" ::: "memory")
#define CP_WAIT1()  asm volatile("cp.async.wait_group 1;" ::: "memory")
#define CP_WAIT0()  asm volatile("cp.async.wait_group 0;" ::: "memory")

// pack (hi_val -> upper 16, lo_val -> lower 16)
__device__ __forceinline__ uint32_t pack2(float lo_f, float hi_f) {
    uint32_t r;
    asm("cvt.rn.bf16x2.f32 %0, %1, %2;" : "=r"(r) : "f"(hi_f), "f"(lo_f));
    return r;
}

// ---------------- prep kernels: split + transpose ----------------
__global__ void prep_w2(const float* __restrict__ W2) {
    int i = blockIdx.x * 256 + threadIdx.x;           // 10*256*128 = 327680
    if (i >= NA * 256 * 128) return;
    int k = i & 127, n = (i >> 7) & 255, a = i >> 15;
    float v = W2[((size_t)a * NH2 + k) * NH + n];
    __nv_bfloat16 h = __float2bfloat16(v);
    __nv_bfloat16 l = __float2bfloat16(v - __bfloat162float(h));
    size_t o = ((size_t)a * 256 + n) * 128 + k;
    g_w2t[o] = h;
    g_w2t[(size_t)NA * 256 * 128 + o] = l;
}
__global__ void prep_w3(const float* __restrict__ W3) {
    int i = blockIdx.x * 256 + threadIdx.x;           // 10*200*256 = 512000
    if (i >= NA * 200 * 256) return;
    int k = i & 255, n = (i >> 8) % 200, a = i / (200 * 256);
    float v = W3[((size_t)a * NH + k) * NF + n];
    __nv_bfloat16 h = __float2bfloat16(v);
    __nv_bfloat16 l = __float2bfloat16(v - __bfloat162float(h));
    size_t o = ((size_t)a * 200 + n) * 256 + k;
    g_w3t[o] = h;
    g_w3t[(size_t)NA * 200 * 256 + o] = l;
}

// ---------------- GEMM chunk: 3 passes (hh, lh, hl), k=32 ----------------
template <int TOT, int MAXT>
__device__ __forceinline__ void gemm_chunk(float (&c)[4][8][4], uint32_t aBaseU,
                                           uint32_t bStageU, int kc, int lane,
                                           int mrow0, int ng) {
#pragma unroll
    for (int p = 0; p < 3; p++) {
        const int at = (p == 1) ? 1 : 0;
        const int bt = (p == 2) ? 1 : 0;
        const uint32_t aPlane = aBaseU + at * APLANE;
        const uint32_t bPlane = bStageU + bt * BTERM;
#pragma unroll
        for (int ks = 0; ks < 2; ks++) {
            const int k0 = kc + ks * 16;
            unsigned af[4][4];
#pragma unroll
            for (int i = 0; i < 4; i++) {
                int row = mrow0 + i * 16 + (lane & 15);
                ldsm_x4(af[i], aPlane + (uint32_t)(row * LDA + k0 + ((lane >> 4) << 3)) * 2);
            }
#pragma unroll
            for (int j = 0; j < MAXT; j++) {
                if (ng + 4 * j < TOT) {          // warp-uniform guard
                    int tn = ng + 4 * j;
                    unsigned bf[2];
                    ldsm_x2(bf, bPlane + (uint32_t)((tn * 8 + (lane & 7)) * LDB +
                                                    ks * 16 + (((lane >> 3) & 1) << 3)) * 2);
#pragma unroll
                    for (int i = 0; i < 4; i++) mma_bf16(c[i][j], af[i], bf);
                }
            }
        }
    }
}

// ---------------- main kernel ----------------
__global__ void __launch_bounds__(256, 1)
main_kernel(const float* __restrict__ x, const float* __restrict__ W1,
            const float* __restrict__ b1, const float* __restrict__ b2,
            const float* __restrict__ b3, const int* __restrict__ idx,
            float* __restrict__ out) {
    extern __shared__ char smem[];
    const uint32_t su = (uint32_t)__cvta_generic_to_shared(smem);

    const int a = blockIdx.y;
    const int n0 = blockIdx.x * TM;
    const int tid = threadIdx.x;
    const int wid = tid >> 5;
    const int lane = tid & 31;
    const int mrow0 = (wid & 1) * 64;
    const int ng = wid >> 1;
    const int g = lane >> 2, tg = lane & 3;

    const __nv_bfloat16* w2a = g_w2t + (size_t)a * 256 * 128;
    const __nv_bfloat16* w3a = g_w3t + (size_t)a * 200 * 256;
    const size_t w2term = (size_t)NA * 256 * 128;
    const size_t w3term = (size_t)NA * 200 * 256;

    // ---- prefetch layer2 chunk0 -> stage0 (before anything else) ----
    {
        const int kc = 0;
#pragma unroll
        for (int it = 0; it < 8; it++) {
            int i = tid + it * 256;                 // 2048 ops
            int term = i >> 10, r = (i >> 2) & 255, seg = i & 3;
            cpa16(su + OFF_B + term * BTERM + r * (LDB * 2) + seg * 16,
                  w2a + term * w2term + (size_t)r * 128 + kc + seg * 8);
        }
        CP_COMMIT();
    }

    // ---- stage s_x, s_w1, biases ----
    float* s_x = (float*)(smem + OFF_X);     // [128][13]
    float* s_w1 = (float*)(smem + OFF_W1);   // [12][128]
    float* s_b2 = (float*)(smem + OFF_BIAS); // [256]
    float* s_b3 = s_b2 + 256;                // [208]
    for (int i = tid; i < TM * NC; i += 256) {
        int t = i / NC, c = i - t * NC;
        s_x[t * 13 + c] = x[(size_t)(n0 + t) * NL + idx[a * NC + c]];
    }
    for (int i = tid; i < NC * NH2; i += 256) s_w1[i] = W1[a * NC * NH2 + i];
    if (tid < 256) s_b2[tid] = b2[a * NH + tid];
    if (tid < 208) s_b3[tid] = (tid < NF) ? b3[a * NF + tid] : 0.0f;
    __syncthreads();

    // ---- layer 1 (fp32 scalar): h1 = relu(xg@W1+b1) -> A2 hi/lo planes ----
    {
        const int t = tid & 127;
        const int hbase = (tid >> 7) * 64;
        float acc[64];
#pragma unroll
        for (int j = 0; j < 64; j++) acc[j] = b1[a * NH2 + hbase + j];
#pragma unroll
        for (int c = 0; c < NC; c++) {
            float xv = s_x[t * 13 + c];
            const float4* wr = (const float4*)(s_w1 + c * NH2 + hbase);
#pragma unroll
            for (int q = 0; q < 16; q++) {
                float4 w = wr[q];
                acc[q * 4 + 0] = fmaf(xv, w.x, acc[q * 4 + 0]);
                acc[q * 4 + 1] = fmaf(xv, w.y, acc[q * 4 + 1]);
                acc[q * 4 + 2] = fmaf(xv, w.z, acc[q * 4 + 2]);
                acc[q * 4 + 3] = fmaf(xv, w.w, acc[q * 4 + 3]);
            }
        }
        uint32_t* Ah = (uint32_t*)(smem + OFF_A + (size_t)t * (LDA * 2) + hbase * 2);
        uint32_t* Al = (uint32_t*)(smem + OFF_A + APLANE + (size_t)t * (LDA * 2) + hbase * 2);
#pragma unroll
        for (int q = 0; q < 32; q++) {
            float v0 = fmaxf(acc[2 * q], 0.0f), v1 = fmaxf(acc[2 * q + 1], 0.0f);
            float h0 = __bfloat162float(__float2bfloat16(v0));
            float h1 = __bfloat162float(__float2bfloat16(v1));
            Ah[q] = pack2(h0, h1);
            Al[q] = pack2(v0 - h0, v1 - h1);
        }
    }
    __syncthreads();

    float cacc[4][8][4];
#pragma unroll
    for (int i = 0; i < 4; i++)
#pragma unroll
        for (int j = 0; j < 8; j++)
#pragma unroll
            for (int q = 0; q < 4; q++) cacc[i][j][q] = 0.0f;

    // ---- layer 2: C2[128x256] = A2[128x128] @ W2, k-chunks of 32 ----
    for (int c = 0; c < 4; c++) {
        if (c < 3) {  // prefetch next layer2 chunk
            const int kc = (c + 1) * 32;
            const uint32_t st = su + OFF_B + ((c + 1) & 1) * BSTAGE;
#pragma unroll
            for (int it = 0; it < 8; it++) {
                int i = tid + it * 256;
                int term = i >> 10, r = (i >> 2) & 255, seg = i & 3;
                cpa16(st + term * BTERM + r * (LDB * 2) + seg * 16,
                      w2a + term * w2term + (size_t)r * 128 + kc + seg * 8);
            }
            CP_COMMIT();
        } else {      // prefetch layer3 chunk0 -> stage0
#pragma unroll
            for (int it = 0; it < 7; it++) {
                int i = tid + it * 256;
                if (i < 1600) {
                    int term = i / 800, rr = i - term * 800;
                    int r = rr >> 2, seg = rr & 3;
                    cpa16(su + OFF_B + term * BTERM + r * (LDB * 2) + seg * 16,
                          w3a + term * w3term + (size_t)r * 256 + 0 + seg * 8);
                }
            }
            CP_COMMIT();
        }
        CP_WAIT1();
        __syncthreads();
        gemm_chunk<32, 8>(cacc, su + OFF_A, su + OFF_B + (c & 1) * BSTAGE,
                          c * 32, lane, mrow0, ng);
        __syncthreads();
    }

    // ---- epilogue 2: bias+relu+split -> A3 planes (overwrites A2) ----
    {
#pragma unroll
        for (int i = 0; i < 4; i++) {
#pragma unroll
            for (int j = 0; j < 8; j++) {
                int col = (ng + 4 * j) * 8 + tg * 2;
                float bb0 = s_b2[col], bb1 = s_b2[col + 1];
                int r0 = mrow0 + i * 16 + g;
#pragma unroll
                for (int half = 0; half < 2; half++) {
                    int r = r0 + half * 8;
                    float v0 = fmaxf(cacc[i][j][2 * half + 0] + bb0, 0.0f);
                    float v1 = fmaxf(cacc[i][j][2 * half + 1] + bb1, 0.0f);
                    float h0 = __bfloat162float(__float2bfloat16(v0));
                    float h1 = __bfloat162float(__float2bfloat16(v1));
                    *(uint32_t*)(smem + OFF_A + (size_t)r * (LDA * 2) + col * 2) =
                        pack2(h0, h1);
                    *(uint32_t*)(smem + OFF_A + APLANE + (size_t)r * (LDA * 2) + col * 2) =
                        pack2(v0 - h0, v1 - h1);
                }
            }
        }
    }
    // (visibility of A3 ensured by the __syncthreads in the layer3 loop below)

#pragma unroll
    for (int i = 0; i < 4; i++)
#pragma unroll
        for (int j = 0; j < 8; j++)
#pragma unroll
            for (int q = 0; q < 4; q++) cacc[i][j][q] = 0.0f;

    // ---- layer 3: C3[128x200] = A3[128x256] @ W3, 8 k-chunks of 32 ----
    for (int c = 0; c < 8; c++) {
        if (c < 7) {
            const int kc = (c + 1) * 32;
            const uint32_t st = su + OFF_B + ((c + 1) & 1) * BSTAGE;
#pragma unroll
            for (int it = 0; it < 7; it++) {
                int i = tid + it * 256;
                if (i < 1600) {
                    int term = i / 800, rr = i - term * 800;
                    int r = rr >> 2, seg = rr & 3;
                    cpa16(st + term * BTERM + r * (LDB * 2) + seg * 16,
                          w3a + term * w3term + (size_t)r * 256 + kc + seg * 8);
                }
            }
            CP_COMMIT();
            CP_WAIT1();
        } else {
            CP_WAIT0();
        }
        __syncthreads();
        gemm_chunk<25, 7>(cacc, su + OFF_A, su + OFF_B + (c & 1) * BSTAGE,
                          c * 32, lane, mrow0, ng);
        __syncthreads();
    }

    // ---- epilogue 3: bias add, store fragments directly (f32 out) ----
    {
#pragma unroll
        for (int i = 0; i < 4; i++) {
#pragma unroll
            for (int j = 0; j < 7; j++) {
                int tn = ng + 4 * j;
                if (tn < 25) {
                    int col = tn * 8 + tg * 2;
                    float bb0 = s_b3[col], bb1 = s_b3[col + 1];
                    int r0 = mrow0 + i * 16 + g;
#pragma unroll
                    for (int half = 0; half < 2; half++) {
                        int r = r0 + half * 8;
                        float2 v = make_float2(cacc[i][j][2 * half + 0] + bb0,
                                               cacc[i][j][2 * half + 1] + bb1);
                        *(float2*)&out[((size_t)(n0 + r) * NA + a) * NF + col] = v;
                    }
                }
            }
        }
    }
}

// ---------------- launch ----------------
extern "C" void kernel_launch(void* const* d_in, const int* in_sizes, int n_in,
                              void* d_out, int out_size) {
    const float *x = nullptr, *W1 = nullptr, *b1 = nullptr, *W2 = nullptr,
                *b2 = nullptr, *W3 = nullptr, *b3 = nullptr;
    const int* idx = nullptr;
    for (int i = 0; i < n_in; i++) {
        switch (in_sizes[i]) {
            case NTOK * NL:     x   = (const float*)d_in[i]; break;
            case NA * NC * NH2: W1  = (const float*)d_in[i]; break;
            case NA * NH2:      b1  = (const float*)d_in[i]; break;
            case NA * NH2 * NH: W2  = (const float*)d_in[i]; break;
            case NA * NH:       b2  = (const float*)d_in[i]; break;
            case NA * NH * NF:  W3  = (const float*)d_in[i]; break;
            case NA * NF:       b3  = (const float*)d_in[i]; break;
            case NA * NC:       idx = (const int*)d_in[i];   break;
            default: break;
        }
    }

    prep_w2<<<(NA * 256 * 128 + 255) / 256, 256>>>(W2);
    prep_w3<<<(NA * 200 * 256 + 255) / 256, 256>>>(W3);

    cudaFuncSetAttribute(main_kernel,
                         cudaFuncAttributeMaxDynamicSharedMemorySize, SMEM_REQ);
    dim3 grid(NTOK / TM, NA);
    main_kernel<<<grid, 256, SMEM_REQ>>>(x, W1, b1, b2, b3, idx, (float*)d_out);
}

// round 5
// speedup vs baseline: 3.5322x; 1.0320x over previous
#include <cuda_runtime.h>
#include <cuda_bf16.h>
#include <cstdint>
#include <cstddef>

// MultiDecoder: A=10 MLPs 12->128->256->200 over 32768 tokens.
// fp32 scalar layer1 + bf16 two-term-split mma.sync (m16n8k16) layers 2 & 3.
// R5: 2 CTAs/SM (TM=64, 110KB smem, <=128 regs), per-term B double buffering.
// CTA = (articulator, 64 tokens), 8 warps = (2 m-halves of 32) x (4 n-groups).

#define NA 10
#define NC 12
#define NH2 128
#define NH 256
#define NF 200
#define NL 120
#define NTOK 32768
#define TM 64

// smem layout (bytes):
//   A planes: 2 x [64 rows][512B, 16B-XOR swizzle] = 65536   @ 0
//   B bufs:   2 x [256 n][80B pitch, 32 k bf16]    = 40960   @ 65536 (BH), 86016 (BL)
//   s_w1:     12*128 floats                        = 6144    @ 106496
#define APLANE 32768
#define OFF_BH 65536
#define OFF_BL 86016
#define OFF_W1 106496
#define SMEM_REQ 112640

#define ASWZ(row, byte) ((unsigned)(byte) ^ (((unsigned)(row) & 7u) << 4))

// weights pre-split (hi/lo bf16) and pre-transposed to [n][k]
__device__ __align__(16) __nv_bfloat16 g_w2t[2 * NA * 256 * 128]; // [term][a][n=256][k=128]
__device__ __align__(16) __nv_bfloat16 g_w3t[2 * NA * 200 * 256]; // [term][a][n=200][k=256]

// ---------------- PTX helpers (base-target only) ----------------
__device__ __forceinline__ void mma_bf16(float* c, const unsigned* a, const unsigned* b) {
    asm volatile("mma.sync.aligned.m16n8k16.row.col.f32.bf16.bf16.f32 "
                 "{%0,%1,%2,%3}, {%4,%5,%6,%7}, {%8,%9}, {%0,%1,%2,%3};"
                 : "+f"(c[0]), "+f"(c[1]), "+f"(c[2]), "+f"(c[3])
                 : "r"(a[0]), "r"(a[1]), "r"(a[2]), "r"(a[3]), "r"(b[0]), "r"(b[1]));
}
__device__ __forceinline__ void ldsm_x4(unsigned* r, uint32_t addr) {
    asm volatile("ldmatrix.sync.aligned.m8n8.x4.shared.b16 {%0,%1,%2,%3}, [%4];"
                 : "=r"(r[0]), "=r"(r[1]), "=r"(r[2]), "=r"(r[3]) : "r"(addr));
}
__device__ __forceinline__ void ldsm_x2(unsigned* r, uint32_t addr) {
    asm volatile("ldmatrix.sync.aligned.m8n8.x2.shared.b16 {%0,%1}, [%2];"
                 : "=r"(r[0]), "=r"(r[1]) : "r"(addr));
}
__device__ __forceinline__ void cpa16(uint32_t dst, const void* src) {
    asm volatile("cp.async.cg.shared.global [%0], [%1], 16;" ::"r"(dst), "l"(src) : "memory");
}
#define CP_COMMIT() asm volatile("cp.async.commit_group;" ::: "memory")
#define CP_WAIT1()  asm volatile("cp.async.wait_group 1;" ::: "memory")
#define CP_WAIT0()  asm volatile("cp.async.wait_group 0;" ::: "memory")

__device__ __forceinline__ uint32_t pack2(float lo_f, float hi_f) {
    uint32_t r;
    asm("cvt.rn.bf16x2.f32 %0, %1, %2;" : "=r"(r) : "f"(hi_f), "f"(lo_f));
    return r;
}

// ---------------- prep kernels: split + transpose ----------------
__global__ void prep_w2(const float* __restrict__ W2) {
    int i = blockIdx.x * 256 + threadIdx.x;           // 10*256*128 = 327680
    if (i >= NA * 256 * 128) return;
    int k = i & 127, n = (i >> 7) & 255, a = i >> 15;
    float v = W2[((size_t)a * NH2 + k) * NH + n];
    __nv_bfloat16 h = __float2bfloat16(v);
    __nv_bfloat16 l = __float2bfloat16(v - __bfloat162float(h));
    size_t o = ((size_t)a * 256 + n) * 128 + k;
    g_w2t[o] = h;
    g_w2t[(size_t)NA * 256 * 128 + o] = l;
}
__global__ void prep_w3(const float* __restrict__ W3) {
    int i = blockIdx.x * 256 + threadIdx.x;           // 10*200*256 = 512000
    if (i >= NA * 200 * 256) return;
    int k = i & 255, n = (i >> 8) % 200, a = i / (200 * 256);
    float v = W3[((size_t)a * NH + k) * NF + n];
    __nv_bfloat16 h = __float2bfloat16(v);
    __nv_bfloat16 l = __float2bfloat16(v - __bfloat162float(h));
    size_t o = ((size_t)a * 200 + n) * 256 + k;
    g_w3t[o] = h;
    g_w3t[(size_t)NA * 200 * 256 + o] = l;
}

// ---------------- B tile loader: one term, k-chunk of 32 ----------------
__device__ __forceinline__ void load_btile(uint32_t dstU, const __nv_bfloat16* src,
                                           int Kst, int rows, int tid) {
#pragma unroll
    for (int it = 0; it < 4; it++) {
        int i = tid + it * 256;
        if (i < rows * 4) {
            int r = i >> 2, seg = i & 3;
            cpa16(dstU + (unsigned)(r * 80 + seg * 16), src + (size_t)r * Kst + seg * 8);
        }
    }
    CP_COMMIT();
}

// ---------------- one split-pass over a k=32 chunk ----------------
template <int TOT, int MAXT>
__device__ __forceinline__ void gemm_pass(float (&c)[2][8][4], uint32_t aPlane,
                                          uint32_t bBuf, int kc, int lane,
                                          int mrow0, int ng) {
#pragma unroll
    for (int ks = 0; ks < 2; ks++) {
        const int k0 = kc + ks * 16;
        unsigned af[2][4];
#pragma unroll
        for (int i = 0; i < 2; i++) {
            int row = mrow0 + i * 16 + (lane & 15);
            ldsm_x4(af[i], aPlane + (unsigned)(row * 512) +
                               ASWZ(row, (k0 + ((lane >> 4) << 3)) * 2));
        }
#pragma unroll
        for (int j = 0; j < MAXT; j++) {
            int tn = ng + 4 * j;
            if (tn < TOT) {                   // warp-uniform guard
                unsigned bf[2];
                ldsm_x2(bf, bBuf + (unsigned)((tn * 8 + (lane & 7)) * 80 +
                                              (ks * 16 + (((lane >> 3) & 1) << 3)) * 2));
                mma_bf16(c[0][j], af[0], bf);
                mma_bf16(c[1][j], af[1], bf);
            }
        }
    }
}

// ---------------- main kernel ----------------
__global__ void __launch_bounds__(256, 2)
main_kernel(const float* __restrict__ x, const float* __restrict__ W1,
            const float* __restrict__ b1, const float* __restrict__ b2,
            const float* __restrict__ b3, const int* __restrict__ idx,
            float* __restrict__ out) {
    extern __shared__ char smem[];
    const uint32_t su = (uint32_t)__cvta_generic_to_shared(smem);

    const int a = blockIdx.y;
    const int n0 = blockIdx.x * TM;
    const int tid = threadIdx.x;
    const int wid = tid >> 5;
    const int lane = tid & 31;
    const int mrow0 = (wid & 1) * 32;
    const int ng = wid >> 1;
    const int g = lane >> 2, tg = lane & 3;

    const __nv_bfloat16* w2a = g_w2t + (size_t)a * 256 * 128;
    const __nv_bfloat16* w3a = g_w3t + (size_t)a * 200 * 256;
    const size_t w2term = (size_t)NA * 256 * 128;
    const size_t w3term = (size_t)NA * 200 * 256;

    // ---- prologue: start Bh(0), Bl(0) of layer2 ----
    load_btile(su + OFF_BH, w2a, 128, 256, tid);
    load_btile(su + OFF_BL, w2a + w2term, 128, 256, tid);

    // ---- stage W1 ----
    float* s_w1 = (float*)(smem + OFF_W1);   // [12][128]
    for (int i = tid; i < NC * NH2; i += 256) s_w1[i] = W1[a * NC * NH2 + i];
    __syncthreads();

    // ---- layer 1 (fp32 scalar): h1 = relu(xg@W1+b1) -> Ah/Al planes ----
    {
        const int t = tid & 63;
        const int hb = (tid >> 6) * 32;      // 4 groups of 32 h-values
        const int* idxa = idx + a * NC;
        float xv[NC];
#pragma unroll
        for (int c = 0; c < NC; c++)
            xv[c] = __ldg(&x[(size_t)(n0 + t) * NL + __ldg(&idxa[c])]);
        float acc[32];
#pragma unroll
        for (int j = 0; j < 32; j++) acc[j] = __ldg(&b1[a * NH2 + hb + j]);
#pragma unroll
        for (int c = 0; c < NC; c++) {
            const float4* wr = (const float4*)(s_w1 + c * NH2 + hb);
#pragma unroll
            for (int q = 0; q < 8; q++) {
                float4 w = wr[q];
                acc[q * 4 + 0] = fmaf(xv[c], w.x, acc[q * 4 + 0]);
                acc[q * 4 + 1] = fmaf(xv[c], w.y, acc[q * 4 + 1]);
                acc[q * 4 + 2] = fmaf(xv[c], w.z, acc[q * 4 + 2]);
                acc[q * 4 + 3] = fmaf(xv[c], w.w, acc[q * 4 + 3]);
            }
        }
        char* rowp = smem + (size_t)t * 512;
#pragma unroll
        for (int q = 0; q < 16; q++) {
            float v0 = fmaxf(acc[2 * q], 0.0f), v1 = fmaxf(acc[2 * q + 1], 0.0f);
            float h0 = __bfloat162float(__float2bfloat16(v0));
            float h1 = __bfloat162float(__float2bfloat16(v1));
            unsigned off = ASWZ(t, hb * 2 + q * 4);
            *(uint32_t*)(rowp + off) = pack2(h0, h1);
            *(uint32_t*)(rowp + APLANE + off) = pack2(v0 - h0, v1 - h1);
        }
    }

    float cacc[2][8][4];
#pragma unroll
    for (int i = 0; i < 2; i++)
#pragma unroll
        for (int j = 0; j < 8; j++)
#pragma unroll
            for (int q = 0; q < 4; q++) cacc[i][j][q] = 0.0f;

    // ---- layer 2: C2[64x256] = A2[64x128] @ W2, 4 k-chunks of 32 ----
    for (int c = 0; c < 4; c++) {
        const int kc = c * 32;
        CP_WAIT1();               // Bh(c) ready (Bl(c) may be pending)
        __syncthreads();
        gemm_pass<32, 8>(cacc, su, su + OFF_BH, kc, lane, mrow0, ng);          // Ah*Bh
        gemm_pass<32, 8>(cacc, su + APLANE, su + OFF_BH, kc, lane, mrow0, ng); // Al*Bh
        __syncthreads();          // BH free
        if (c < 3) load_btile(su + OFF_BH, w2a + (size_t)(kc + 32), 128, 256, tid);
        else       load_btile(su + OFF_BH, w3a, 256, 200, tid);                // l3 Bh(0)
        CP_WAIT1();               // Bl(c) ready (next Bh pending)
        __syncthreads();
        gemm_pass<32, 8>(cacc, su, su + OFF_BL, kc, lane, mrow0, ng);          // Ah*Bl
        __syncthreads();          // BL free
        if (c < 3) load_btile(su + OFF_BL, w2a + w2term + (size_t)(kc + 32), 128, 256, tid);
        else       load_btile(su + OFF_BL, w3a + w3term, 256, 200, tid);       // l3 Bl(0)
    }

    // ---- epilogue 2: bias+relu+split -> A3 planes (overwrites A2) ----
    {
#pragma unroll
        for (int i = 0; i < 2; i++) {
#pragma unroll
            for (int j = 0; j < 8; j++) {
                int col = (ng + 4 * j) * 8 + tg * 2;
                float bb0 = __ldg(&b2[a * NH + col]);
                float bb1 = __ldg(&b2[a * NH + col + 1]);
                int r0 = mrow0 + i * 16 + g;
#pragma unroll
                for (int half = 0; half < 2; half++) {
                    int r = r0 + half * 8;
                    float v0 = fmaxf(cacc[i][j][2 * half + 0] + bb0, 0.0f);
                    float v1 = fmaxf(cacc[i][j][2 * half + 1] + bb1, 0.0f);
                    float h0 = __bfloat162float(__float2bfloat16(v0));
                    float h1 = __bfloat162float(__float2bfloat16(v1));
                    unsigned off = ASWZ(r, col * 2);
                    char* rowp = smem + (size_t)r * 512;
                    *(uint32_t*)(rowp + off) = pack2(h0, h1);
                    *(uint32_t*)(rowp + APLANE + off) = pack2(v0 - h0, v1 - h1);
                }
            }
        }
    }

#pragma unroll
    for (int i = 0; i < 2; i++)
#pragma unroll
        for (int j = 0; j < 8; j++)
#pragma unroll
            for (int q = 0; q < 4; q++) cacc[i][j][q] = 0.0f;

    // ---- layer 3: C3[64x200] = A3[64x256] @ W3, 8 k-chunks of 32 ----
    for (int c = 0; c < 8; c++) {
        const int kc = c * 32;
        CP_WAIT1();
        __syncthreads();          // also covers epilogue2 writes on c==0
        gemm_pass<25, 7>(cacc, su, su + OFF_BH, kc, lane, mrow0, ng);
        gemm_pass<25, 7>(cacc, su + APLANE, su + OFF_BH, kc, lane, mrow0, ng);
        __syncthreads();
        if (c < 7) load_btile(su + OFF_BH, w3a + (size_t)(kc + 32), 256, 200, tid);
        if (c < 7) CP_WAIT1(); else CP_WAIT0();
        __syncthreads();
        gemm_pass<25, 7>(cacc, su, su + OFF_BL, kc, lane, mrow0, ng);
        __syncthreads();
        if (c < 7) load_btile(su + OFF_BL, w3a + w3term + (size_t)(kc + 32), 256, 200, tid);
    }

    // ---- epilogue 3: bias add, store fragments directly (f32 out) ----
    {
#pragma unroll
        for (int i = 0; i < 2; i++) {
#pragma unroll
            for (int j = 0; j < 7; j++) {
                int tn = ng + 4 * j;
                if (tn < 25) {
                    int col = tn * 8 + tg * 2;
                    float bb0 = __ldg(&b3[a * NF + col]);
                    float bb1 = __ldg(&b3[a * NF + col + 1]);
                    int r0 = mrow0 + i * 16 + g;
#pragma unroll
                    for (int half = 0; half < 2; half++) {
                        int r = r0 + half * 8;
                        float2 v = make_float2(cacc[i][j][2 * half + 0] + bb0,
                                               cacc[i][j][2 * half + 1] + bb1);
                        *(float2*)&out[((size_t)(n0 + r) * NA + a) * NF + col] = v;
                    }
                }
            }
        }
    }
}

// ---------------- launch ----------------
extern "C" void kernel_launch(void* const* d_in, const int* in_sizes, int n_in,
                              void* d_out, int out_size) {
    const float *x = nullptr, *W1 = nullptr, *b1 = nullptr, *W2 = nullptr,
                *b2 = nullptr, *W3 = nullptr, *b3 = nullptr;
    const int* idx = nullptr;
    for (int i = 0; i < n_in; i++) {
        switch (in_sizes[i]) {
            case NTOK * NL:     x   = (const float*)d_in[i]; break;
            case NA * NC * NH2: W1  = (const float*)d_in[i]; break;
            case NA * NH2:      b1  = (const float*)d_in[i]; break;
            case NA * NH2 * NH: W2  = (const float*)d_in[i]; break;
            case NA * NH:       b2  = (const float*)d_in[i]; break;
            case NA * NH * NF:  W3  = (const float*)d_in[i]; break;
            case NA * NF:       b3  = (const float*)d_in[i]; break;
            case NA * NC:       idx = (const int*)d_in[i];   break;
            default: break;
        }
    }

    prep_w2<<<(NA * 256 * 128 + 255) / 256, 256>>>(W2);
    prep_w3<<<(NA * 200 * 256 + 255) / 256, 256>>>(W3);

    cudaFuncSetAttribute(main_kernel,
                         cudaFuncAttributeMaxDynamicSharedMemorySize, SMEM_REQ);
    dim3 grid(NTOK / TM, NA);
    main_kernel<<<grid, 256, SMEM_REQ>>>(x, W1, b1, b2, b3, idx, (float*)d_out);
}

// round 6
// speedup vs baseline: 5.2489x; 1.4860x over previous
#include <cuda_runtime.h>
#include <cuda_fp16.h>
#include <cstdint>
#include <cstddef>

// MultiDecoder: A=10 MLPs 12->128->256->200 over 32768 tokens.
// fp32 scalar layer1 + fp16 split-activation mma.sync (m16n8k16) layers 2 & 3.
// R6: 2 passes/chunk (Ah*B + Al*B, B single fp16) -- mma.sync issue ceiling is
// ~512 MAC/cyc/SM, so cut issued MACs 3->2 passes. 2 CTAs/SM, TM=64.

#define NA 10
#define NC 12
#define NH2 128
#define NH 256
#define NF 200
#define NL 120
#define NTOK 32768
#define TM 64

// smem layout (bytes):
//   A planes: 2 x [64 rows][512B, 16B-XOR swizzle] = 65536   @ 0
//   B stages: 2 x [256 n][80B pitch, 32 k fp16]    = 40960   @ 65536, 86016
//   s_w1:     12*128 floats                        = 6144    @ 106496
#define APLANE 32768
#define OFF_B0 65536
#define OFF_B1 86016
#define OFF_W1 106496
#define SMEM_REQ 112640

#define ASWZ(row, byte) ((unsigned)(byte) ^ (((unsigned)(row) & 7u) << 4))

// weights fp16, pre-transposed to [n][k] (single term)
__device__ __align__(16) __half g_w2t[NA * 256 * 128];  // [a][n=256][k=128]
__device__ __align__(16) __half g_w3t[NA * 200 * 256];  // [a][n=200][k=256]

// ---------------- PTX helpers (base-target only) ----------------
__device__ __forceinline__ void mma_f16(float* c, const unsigned* a, const unsigned* b) {
    asm volatile("mma.sync.aligned.m16n8k16.row.col.f32.f16.f16.f32 "
                 "{%0,%1,%2,%3}, {%4,%5,%6,%7}, {%8,%9}, {%0,%1,%2,%3};"
                 : "+f"(c[0]), "+f"(c[1]), "+f"(c[2]), "+f"(c[3])
                 : "r"(a[0]), "r"(a[1]), "r"(a[2]), "r"(a[3]), "r"(b[0]), "r"(b[1]));
}
__device__ __forceinline__ void ldsm_x4(unsigned* r, uint32_t addr) {
    asm volatile("ldmatrix.sync.aligned.m8n8.x4.shared.b16 {%0,%1,%2,%3}, [%4];"
                 : "=r"(r[0]), "=r"(r[1]), "=r"(r[2]), "=r"(r[3]) : "r"(addr));
}
__device__ __forceinline__ void ldsm_x2(unsigned* r, uint32_t addr) {
    asm volatile("ldmatrix.sync.aligned.m8n8.x2.shared.b16 {%0,%1}, [%2];"
                 : "=r"(r[0]), "=r"(r[1]) : "r"(addr));
}
__device__ __forceinline__ void cpa16(uint32_t dst, const void* src) {
    asm volatile("cp.async.cg.shared.global [%0], [%1], 16;" ::"r"(dst), "l"(src) : "memory");
}
#define CP_COMMIT() asm volatile("cp.async.commit_group;" ::: "memory")
#define CP_WAIT1()  asm volatile("cp.async.wait_group 1;" ::: "memory")
#define CP_WAIT0()  asm volatile("cp.async.wait_group 0;" ::: "memory")

// pack two floats -> f16x2 (hi_f -> upper 16 bits, lo_f -> lower 16 bits)
__device__ __forceinline__ uint32_t pack2h(float lo_f, float hi_f) {
    uint32_t r;
    asm("cvt.rn.f16x2.f32 %0, %1, %2;" : "=r"(r) : "f"(hi_f), "f"(lo_f));
    return r;
}

// ---------------- prep kernels: fp16 convert + transpose ----------------
__global__ void prep_w2(const float* __restrict__ W2) {
    int i = blockIdx.x * 256 + threadIdx.x;           // 10*256*128 = 327680
    if (i >= NA * 256 * 128) return;
    int k = i & 127, n = (i >> 7) & 255, a = i >> 15;
    g_w2t[((size_t)a * 256 + n) * 128 + k] =
        __float2half_rn(W2[((size_t)a * NH2 + k) * NH + n]);
}
__global__ void prep_w3(const float* __restrict__ W3) {
    int i = blockIdx.x * 256 + threadIdx.x;           // 10*200*256 = 512000
    if (i >= NA * 200 * 256) return;
    int k = i & 255, n = (i >> 8) % 200, a = i / (200 * 256);
    g_w3t[((size_t)a * 200 + n) * 256 + k] =
        __float2half_rn(W3[((size_t)a * NH + k) * NF + n]);
}

// ---------------- B tile loader: k-chunk of 32, one commit group ----------------
__device__ __forceinline__ void load_btile(uint32_t dstU, const __half* src,
                                           int Kst, int rows, int tid) {
#pragma unroll
    for (int it = 0; it < 4; it++) {
        int i = tid + it * 256;
        if (i < rows * 4) {
            int r = i >> 2, seg = i & 3;
            cpa16(dstU + (unsigned)(r * 80 + seg * 16), src + (size_t)r * Kst + seg * 8);
        }
    }
    CP_COMMIT();
}

// ---------------- both split-passes over a k=32 chunk ----------------
// Loads each B fragment once, feeds both A planes (hi then lo).
template <int TOT, int MAXT>
__device__ __forceinline__ void gemm_chunk(float (&c)[2][8][4], uint32_t su,
                                           uint32_t bBuf, int kc, int lane,
                                           int mrow0, int ng) {
#pragma unroll
    for (int ks = 0; ks < 2; ks++) {
        const int k0 = kc + ks * 16;
        unsigned af[2][2][4];                 // [plane][mtile][frag]
#pragma unroll
        for (int p = 0; p < 2; p++)
#pragma unroll
            for (int i = 0; i < 2; i++) {
                int row = mrow0 + i * 16 + (lane & 15);
                ldsm_x4(af[p][i], su + p * APLANE + (unsigned)(row * 512) +
                                      ASWZ(row, (k0 + ((lane >> 4) << 3)) * 2));
            }
#pragma unroll
        for (int j = 0; j < MAXT; j++) {
            int tn = ng + 4 * j;
            if (tn < TOT) {                   // warp-uniform guard
                unsigned bf[2];
                ldsm_x2(bf, bBuf + (unsigned)((tn * 8 + (lane & 7)) * 80 +
                                              (ks * 16 + (((lane >> 3) & 1) << 3)) * 2));
                mma_f16(c[0][j], af[0][0], bf);
                mma_f16(c[1][j], af[0][1], bf);
                mma_f16(c[0][j], af[1][0], bf);
                mma_f16(c[1][j], af[1][1], bf);
            }
        }
    }
}

// ---------------- main kernel ----------------
__global__ void __launch_bounds__(256, 2)
main_kernel(const float* __restrict__ x, const float* __restrict__ W1,
            const float* __restrict__ b1, const float* __restrict__ b2,
            const float* __restrict__ b3, const int* __restrict__ idx,
            float* __restrict__ out) {
    extern __shared__ char smem[];
    const uint32_t su = (uint32_t)__cvta_generic_to_shared(smem);

    const int a = blockIdx.y;
    const int n0 = blockIdx.x * TM;
    const int tid = threadIdx.x;
    const int wid = tid >> 5;
    const int lane = tid & 31;
    const int mrow0 = (wid & 1) * 32;
    const int ng = wid >> 1;
    const int g = lane >> 2, tg = lane & 3;

    const __half* w2a = g_w2t + (size_t)a * 256 * 128;
    const __half* w3a = g_w3t + (size_t)a * 200 * 256;

    // ---- prologue: start layer2 chunks 0,1 into stages 0,1 ----
    load_btile(su + OFF_B0, w2a, 128, 256, tid);
    load_btile(su + OFF_B1, w2a + 32, 128, 256, tid);

    // ---- stage W1 ----
    float* s_w1 = (float*)(smem + OFF_W1);   // [12][128]
    for (int i = tid; i < NC * NH2; i += 256) s_w1[i] = W1[a * NC * NH2 + i];
    __syncthreads();

    // ---- layer 1 (fp32 scalar): h1 = relu(xg@W1+b1) -> Ah/Al planes ----
    {
        const int t = tid & 63;
        const int hb = (tid >> 6) * 32;      // 4 groups of 32 h-values
        const int* idxa = idx + a * NC;
        float xv[NC];
#pragma unroll
        for (int c = 0; c < NC; c++)
            xv[c] = __ldg(&x[(size_t)(n0 + t) * NL + __ldg(&idxa[c])]);
        float acc[32];
#pragma unroll
        for (int j = 0; j < 32; j++) acc[j] = __ldg(&b1[a * NH2 + hb + j]);
#pragma unroll
        for (int c = 0; c < NC; c++) {
            const float4* wr = (const float4*)(s_w1 + c * NH2 + hb);
#pragma unroll
            for (int q = 0; q < 8; q++) {
                float4 w = wr[q];
                acc[q * 4 + 0] = fmaf(xv[c], w.x, acc[q * 4 + 0]);
                acc[q * 4 + 1] = fmaf(xv[c], w.y, acc[q * 4 + 1]);
                acc[q * 4 + 2] = fmaf(xv[c], w.z, acc[q * 4 + 2]);
                acc[q * 4 + 3] = fmaf(xv[c], w.w, acc[q * 4 + 3]);
            }
        }
        char* rowp = smem + (size_t)t * 512;
#pragma unroll
        for (int q = 0; q < 16; q++) {
            float v0 = fmaxf(acc[2 * q], 0.0f), v1 = fmaxf(acc[2 * q + 1], 0.0f);
            float h0 = __half2float(__float2half_rn(v0));
            float h1 = __half2float(__float2half_rn(v1));
            unsigned off = ASWZ(t, hb * 2 + q * 4);
            *(uint32_t*)(rowp + off) = pack2h(h0, h1);
            *(uint32_t*)(rowp + APLANE + off) = pack2h(v0 - h0, v1 - h1);
        }
    }

    float cacc[2][8][4];
#pragma unroll
    for (int i = 0; i < 2; i++)
#pragma unroll
        for (int j = 0; j < 8; j++)
#pragma unroll
            for (int q = 0; q < 4; q++) cacc[i][j][q] = 0.0f;

    // ---- layer 2: C2[64x256] = A2[64x128] @ W2, 4 k-chunks of 32 ----
    for (int c = 0; c < 4; c++) {
        const int kc = c * 32;
        CP_WAIT1();               // chunk c resident in stage c&1
        __syncthreads();
        gemm_chunk<32, 8>(cacc, su, su + ((c & 1) ? OFF_B1 : OFF_B0), kc, lane, mrow0, ng);
        __syncthreads();          // stage c&1 free
        int nx = c + 2;
        uint32_t st = su + ((c & 1) ? OFF_B1 : OFF_B0);
        if (nx < 4) load_btile(st, w2a + (size_t)nx * 32, 128, 256, tid);
        else        load_btile(st, w3a + (size_t)(nx - 4) * 32, 256, 200, tid);
    }

    // ---- epilogue 2: bias+relu+split -> A3 planes (overwrites A2) ----
    {
#pragma unroll
        for (int i = 0; i < 2; i++) {
#pragma unroll
            for (int j = 0; j < 8; j++) {
                int col = (ng + 4 * j) * 8 + tg * 2;
                float bb0 = __ldg(&b2[a * NH + col]);
                float bb1 = __ldg(&b2[a * NH + col + 1]);
                int r0 = mrow0 + i * 16 + g;
#pragma unroll
                for (int half = 0; half < 2; half++) {
                    int r = r0 + half * 8;
                    float v0 = fmaxf(cacc[i][j][2 * half + 0] + bb0, 0.0f);
                    float v1 = fmaxf(cacc[i][j][2 * half + 1] + bb1, 0.0f);
                    float h0 = __half2float(__float2half_rn(v0));
                    float h1 = __half2float(__float2half_rn(v1));
                    unsigned off = ASWZ(r, col * 2);
                    char* rowp = smem + (size_t)r * 512;
                    *(uint32_t*)(rowp + off) = pack2h(h0, h1);
                    *(uint32_t*)(rowp + APLANE + off) = pack2h(v0 - h0, v1 - h1);
                }
            }
        }
    }

#pragma unroll
    for (int i = 0; i < 2; i++)
#pragma unroll
        for (int j = 0; j < 8; j++)
#pragma unroll
            for (int q = 0; q < 4; q++) cacc[i][j][q] = 0.0f;

    // ---- layer 3: C3[64x200] = A3[64x256] @ W3, 8 k-chunks of 32 ----
    for (int c = 0; c < 8; c++) {
        const int kc = c * 32;
        if (c < 7) CP_WAIT1(); else CP_WAIT0();
        __syncthreads();          // also orders epilogue2 writes before c==0 reads
        gemm_chunk<25, 7>(cacc, su, su + ((c & 1) ? OFF_B1 : OFF_B0), kc, lane, mrow0, ng);
        __syncthreads();
        int nx = c + 2;
        if (nx < 8)
            load_btile(su + ((c & 1) ? OFF_B1 : OFF_B0),
                       w3a + (size_t)nx * 32, 256, 200, tid);
    }

    // ---- epilogue 3: bias add, store fragments directly (f32 out) ----
    {
#pragma unroll
        for (int i = 0; i < 2; i++) {
#pragma unroll
            for (int j = 0; j < 7; j++) {
                int tn = ng + 4 * j;
                if (tn < 25) {
                    int col = tn * 8 + tg * 2;
                    float bb0 = __ldg(&b3[a * NF + col]);
                    float bb1 = __ldg(&b3[a * NF + col + 1]);
                    int r0 = mrow0 + i * 16 + g;
#pragma unroll
                    for (int half = 0; half < 2; half++) {
                        int r = r0 + half * 8;
                        float2 v = make_float2(cacc[i][j][2 * half + 0] + bb0,
                                               cacc[i][j][2 * half + 1] + bb1);
                        *(float2*)&out[((size_t)(n0 + r) * NA + a) * NF + col] = v;
                    }
                }
            }
        }
    }
}

// ---------------- launch ----------------
extern "C" void kernel_launch(void* const* d_in, const int* in_sizes, int n_in,
                              void* d_out, int out_size) {
    const float *x = nullptr, *W1 = nullptr, *b1 = nullptr, *W2 = nullptr,
                *b2 = nullptr, *W3 = nullptr, *b3 = nullptr;
    const int* idx = nullptr;
    for (int i = 0; i < n_in; i++) {
        switch (in_sizes[i]) {
            case NTOK * NL:     x   = (const float*)d_in[i]; break;
            case NA * NC * NH2: W1  = (const float*)d_in[i]; break;
            case NA * NH2:      b1  = (const float*)d_in[i]; break;
            case NA * NH2 * NH: W2  = (const float*)d_in[i]; break;
            case NA * NH:       b2  = (const float*)d_in[i]; break;
            case NA * NH * NF:  W3  = (const float*)d_in[i]; break;
            case NA * NF:       b3  = (const float*)d_in[i]; break;
            case NA * NC:       idx = (const int*)d_in[i];   break;
            default: break;
        }
    }

    prep_w2<<<(NA * 256 * 128 + 255) / 256, 256>>>(W2);
    prep_w3<<<(NA * 200 * 256 + 255) / 256, 256>>>(W3);

    cudaFuncSetAttribute(main_kernel,
                         cudaFuncAttributeMaxDynamicSharedMemorySize, SMEM_REQ);
    dim3 grid(NTOK / TM, NA);
    main_kernel<<<grid, 256, SMEM_REQ>>>(x, W1, b1, b2, b3, idx, (float*)d_out);
}

// round 8
// speedup vs baseline: 6.9815x; 1.3301x over previous
#include <cuda_runtime.h>
#include <cuda_fp16.h>
#include <cstdint>
#include <cstddef>

// MultiDecoder: A=10 MLPs 12->128->256->200 over 32768 tokens.
// fp32 scalar layer1 + single-pass fp16 mma.sync (m16n8k16) layers 2 & 3
// (fp32 accumulate). R7: mma.sync issue ceiling ~512 MAC/cyc/SM means time
// scales with issued MACs -- drop the A-split correction pass (2 -> 1 pass).
// Error = A-round + W-round ~ sqrt(2)*2.67e-4 ~ 4e-4 < 1e-3.
// CTA = (articulator, 64 tokens), 8 warps, 2 CTAs/SM.

#define NA 10
#define NC 12
#define NH2 128
#define NH 256
#define NF 200
#define NL 120
#define NTOK 32768
#define TM 64

// smem layout (bytes):
//   A plane:  [64 rows][512B, 16B-XOR swizzle]     = 32768   @ 0
//   B stages: 2 x [256 n][80B pitch, 32 k fp16]    = 40960   @ 32768, 53248
//   s_w1:     12*128 floats                        = 6144    @ 73728
#define OFF_B0 32768
#define OFF_B1 53248
#define OFF_W1 73728
#define SMEM_REQ 79872

#define ASWZ(row, byte) ((unsigned)(byte) ^ (((unsigned)(row) & 7u) << 4))

// weights fp16, pre-transposed to [n][k]
__device__ __align__(16) __half g_w2t[NA * 256 * 128];  // [a][n=256][k=128]
__device__ __align__(16) __half g_w3t[NA * 200 * 256];  // [a][n=200][k=256]

// ---------------- PTX helpers (base-target only) ----------------
__device__ __forceinline__ void mma_f16(float* c, const unsigned* a, const unsigned* b) {
    asm volatile("mma.sync.aligned.m16n8k16.row.col.f32.f16.f16.f32 "
                 "{%0,%1,%2,%3}, {%4,%5,%6,%7}, {%8,%9}, {%0,%1,%2,%3};"
                 : "+f"(c[0]), "+f"(c[1]), "+f"(c[2]), "+f"(c[3])
                 : "r"(a[0]), "r"(a[1]), "r"(a[2]), "r"(a[3]), "r"(b[0]), "r"(b[1]));
}
__device__ __forceinline__ void ldsm_x4(unsigned* r, uint32_t addr) {
    asm volatile("ldmatrix.sync.aligned.m8n8.x4.shared.b16 {%0,%1,%2,%3}, [%4];"
                 : "=r"(r[0]), "=r"(r[1]), "=r"(r[2]), "=r"(r[3]) : "r"(addr));
}
__device__ __forceinline__ void ldsm_x2(unsigned* r, uint32_t addr) {
    asm volatile("ldmatrix.sync.aligned.m8n8.x2.shared.b16 {%0,%1}, [%2];"
                 : "=r"(r[0]), "=r"(r[1]) : "r"(addr));
}
__device__ __forceinline__ void cpa16(uint32_t dst, const void* src) {
    asm volatile("cp.async.cg.shared.global [%0], [%1], 16;" ::"r"(dst), "l"(src) : "memory");
}
#define CP_COMMIT() asm volatile("cp.async.commit_group;" ::: "memory")
#define CP_WAIT1()  asm volatile("cp.async.wait_group 1;" ::: "memory")
#define CP_WAIT0()  asm volatile("cp.async.wait_group 0;" ::: "memory")

// pack two floats -> f16x2 (hi_f -> upper 16 bits, lo_f -> lower 16 bits)
__device__ __forceinline__ uint32_t pack2h(float lo_f, float hi_f) {
    uint32_t r;
    asm("cvt.rn.f16x2.f32 %0, %1, %2;" : "=r"(r) : "f"(hi_f), "f"(lo_f));
    return r;
}

// ---------------- prep kernels: fp16 convert + transpose ----------------
__global__ void prep_w2(const float* __restrict__ W2) {
    int i = blockIdx.x * 256 + threadIdx.x;           // 10*256*128 = 327680
    if (i >= NA * 256 * 128) return;
    int k = i & 127, n = (i >> 7) & 255, a = i >> 15;
    g_w2t[((size_t)a * 256 + n) * 128 + k] =
        __float2half_rn(W2[((size_t)a * NH2 + k) * NH + n]);
}
__global__ void prep_w3(const float* __restrict__ W3) {
    int i = blockIdx.x * 256 + threadIdx.x;           // 10*200*256 = 512000
    if (i >= NA * 200 * 256) return;
    int k = i & 255, n = (i >> 8) % 200, a = i / (200 * 256);
    g_w3t[((size_t)a * 200 + n) * 256 + k] =
        __float2half_rn(W3[((size_t)a * NH + k) * NF + n]);
}

// ---------------- B tile loader: k-chunk of 32, one commit group ----------------
__device__ __forceinline__ void load_btile(uint32_t dstU, const __half* src,
                                           int Kst, int rows, int tid) {
#pragma unroll
    for (int it = 0; it < 4; it++) {
        int i = tid + it * 256;
        if (i < rows * 4) {
            int r = i >> 2, seg = i & 3;
            cpa16(dstU + (unsigned)(r * 80 + seg * 16), src + (size_t)r * Kst + seg * 8);
        }
    }
    CP_COMMIT();
}

// ---------------- single pass over a k=32 chunk ----------------
template <int TOT, int MAXT>
__device__ __forceinline__ void gemm_chunk(float (&c)[2][8][4], uint32_t su,
                                           uint32_t bBuf, int kc, int lane,
                                           int mrow0, int ng) {
#pragma unroll
    for (int ks = 0; ks < 2; ks++) {
        const int k0 = kc + ks * 16;
        unsigned af[2][4];
#pragma unroll
        for (int i = 0; i < 2; i++) {
            int row = mrow0 + i * 16 + (lane & 15);
            ldsm_x4(af[i], su + (unsigned)(row * 512) +
                               ASWZ(row, (k0 + ((lane >> 4) << 3)) * 2));
        }
#pragma unroll
        for (int j = 0; j < MAXT; j++) {
            int tn = ng + 4 * j;
            if (tn < TOT) {                   // warp-uniform guard
                unsigned bf[2];
                ldsm_x2(bf, bBuf + (unsigned)((tn * 8 + (lane & 7)) * 80 +
                                              (ks * 16 + (((lane >> 3) & 1) << 3)) * 2));
                mma_f16(c[0][j], af[0], bf);
                mma_f16(c[1][j], af[1], bf);
            }
        }
    }
}

// ---------------- main kernel ----------------
__global__ void __launch_bounds__(256, 2)
main_kernel(const float* __restrict__ x, const float* __restrict__ W1,
            const float* __restrict__ b1, const float* __restrict__ b2,
            const float* __restrict__ b3, const int* __restrict__ idx,
            float* __restrict__ out) {
    extern __shared__ char smem[];
    const uint32_t su = (uint32_t)__cvta_generic_to_shared(smem);

    const int a = blockIdx.y;
    const int n0 = blockIdx.x * TM;
    const int tid = threadIdx.x;
    const int wid = tid >> 5;
    const int lane = tid & 31;
    const int mrow0 = (wid & 1) * 32;
    const int ng = wid >> 1;
    const int g = lane >> 2, tg = lane & 3;

    const __half* w2a = g_w2t + (size_t)a * 256 * 128;
    const __half* w3a = g_w3t + (size_t)a * 200 * 256;

    // ---- prologue: start layer2 chunks 0,1 into stages 0,1 ----
    load_btile(su + OFF_B0, w2a, 128, 256, tid);
    load_btile(su + OFF_B1, w2a + 32, 128, 256, tid);

    // ---- stage W1 ----
    float* s_w1 = (float*)(smem + OFF_W1);   // [12][128]
    for (int i = tid; i < NC * NH2; i += 256) s_w1[i] = W1[a * NC * NH2 + i];
    __syncthreads();

    // ---- layer 1 (fp32 scalar): h1 = relu(xg@W1+b1) -> A plane (fp16) ----
    {
        const int t = tid & 63;
        const int hb = (tid >> 6) * 32;      // 4 groups of 32 h-values
        const int* idxa = idx + a * NC;
        float xv[NC];
#pragma unroll
        for (int c = 0; c < NC; c++)
            xv[c] = __ldg(&x[(size_t)(n0 + t) * NL + __ldg(&idxa[c])]);
        float acc[32];
#pragma unroll
        for (int j = 0; j < 32; j++) acc[j] = __ldg(&b1[a * NH2 + hb + j]);
#pragma unroll
        for (int c = 0; c < NC; c++) {
            const float4* wr = (const float4*)(s_w1 + c * NH2 + hb);
#pragma unroll
            for (int q = 0; q < 8; q++) {
                float4 w = wr[q];
                acc[q * 4 + 0] = fmaf(xv[c], w.x, acc[q * 4 + 0]);
                acc[q * 4 + 1] = fmaf(xv[c], w.y, acc[q * 4 + 1]);
                acc[q * 4 + 2] = fmaf(xv[c], w.z, acc[q * 4 + 2]);
                acc[q * 4 + 3] = fmaf(xv[c], w.w, acc[q * 4 + 3]);
            }
        }
        char* rowp = smem + (size_t)t * 512;
#pragma unroll
        for (int q = 0; q < 16; q++) {
            float v0 = fmaxf(acc[2 * q], 0.0f), v1 = fmaxf(acc[2 * q + 1], 0.0f);
            *(uint32_t*)(rowp + ASWZ(t, hb * 2 + q * 4)) = pack2h(v0, v1);
        }
    }

    float cacc[2][8][4];
#pragma unroll
    for (int i = 0; i < 2; i++)
#pragma unroll
        for (int j = 0; j < 8; j++)
#pragma unroll
            for (int q = 0; q < 4; q++) cacc[i][j][q] = 0.0f;

    // ---- layer 2: C2[64x256] = A2[64x128] @ W2, 4 k-chunks of 32 ----
    for (int c = 0; c < 4; c++) {
        const int kc = c * 32;
        CP_WAIT1();               // chunk c resident in stage c&1
        __syncthreads();
        gemm_chunk<32, 8>(cacc, su, su + ((c & 1) ? OFF_B1 : OFF_B0), kc, lane, mrow0, ng);
        __syncthreads();          // stage c&1 free
        int nx = c + 2;
        uint32_t st = su + ((c & 1) ? OFF_B1 : OFF_B0);
        if (nx < 4) load_btile(st, w2a + (size_t)nx * 32, 128, 256, tid);
        else        load_btile(st, w3a + (size_t)(nx - 4) * 32, 256, 200, tid);
    }

    // ---- epilogue 2: bias+relu -> A3 plane (overwrites A2, fp16) ----
    {
#pragma unroll
        for (int i = 0; i < 2; i++) {
#pragma unroll
            for (int j = 0; j < 8; j++) {
                int col = (ng + 4 * j) * 8 + tg * 2;
                float bb0 = __ldg(&b2[a * NH + col]);
                float bb1 = __ldg(&b2[a * NH + col + 1]);
                int r0 = mrow0 + i * 16 + g;
#pragma unroll
                for (int half = 0; half < 2; half++) {
                    int r = r0 + half * 8;
                    float v0 = fmaxf(cacc[i][j][2 * half + 0] + bb0, 0.0f);
                    float v1 = fmaxf(cacc[i][j][2 * half + 1] + bb1, 0.0f);
                    *(uint32_t*)(smem + (size_t)r * 512 + ASWZ(r, col * 2)) =
                        pack2h(v0, v1);
                }
            }
        }
    }

#pragma unroll
    for (int i = 0; i < 2; i++)
#pragma unroll
        for (int j = 0; j < 8; j++)
#pragma unroll
            for (int q = 0; q < 4; q++) cacc[i][j][q] = 0.0f;

    // ---- layer 3: C3[64x200] = A3[64x256] @ W3, 8 k-chunks of 32 ----
    for (int c = 0; c < 8; c++) {
        const int kc = c * 32;
        if (c < 7) CP_WAIT1(); else CP_WAIT0();
        __syncthreads();          // also orders epilogue2 writes before c==0 reads
        gemm_chunk<25, 7>(cacc, su, su + ((c & 1) ? OFF_B1 : OFF_B0), kc, lane, mrow0, ng);
        __syncthreads();
        int nx = c + 2;
        if (nx < 8)
            load_btile(su + ((c & 1) ? OFF_B1 : OFF_B0),
                       w3a + (size_t)nx * 32, 256, 200, tid);
    }

    // ---- epilogue 3: bias add, store fragments directly (f32 out) ----
    {
#pragma unroll
        for (int i = 0; i < 2; i++) {
#pragma unroll
            for (int j = 0; j < 7; j++) {
                int tn = ng + 4 * j;
                if (tn < 25) {
                    int col = tn * 8 + tg * 2;
                    float bb0 = __ldg(&b3[a * NF + col]);
                    float bb1 = __ldg(&b3[a * NF + col + 1]);
                    int r0 = mrow0 + i * 16 + g;
#pragma unroll
                    for (int half = 0; half < 2; half++) {
                        int r = r0 + half * 8;
                        float2 v = make_float2(cacc[i][j][2 * half + 0] + bb0,
                                               cacc[i][j][2 * half + 1] + bb1);
                        *(float2*)&out[((size_t)(n0 + r) * NA + a) * NF + col] = v;
                    }
                }
            }
        }
    }
}

// ---------------- launch ----------------
extern "C" void kernel_launch(void* const* d_in, const int* in_sizes, int n_in,
                              void* d_out, int out_size) {
    const float *x = nullptr, *W1 = nullptr, *b1 = nullptr, *W2 = nullptr,
                *b2 = nullptr, *W3 = nullptr, *b3 = nullptr;
    const int* idx = nullptr;
    for (int i = 0; i < n_in; i++) {
        switch (in_sizes[i]) {
            case NTOK * NL:     x   = (const float*)d_in[i]; break;
            case NA * NC * NH2: W1  = (const float*)d_in[i]; break;
            case NA * NH2:      b1  = (const float*)d_in[i]; break;
            case NA * NH2 * NH: W2  = (const float*)d_in[i]; break;
            case NA * NH:       b2  = (const float*)d_in[i]; break;
            case NA * NH * NF:  W3  = (const float*)d_in[i]; break;
            case NA * NF:       b3  = (const float*)d_in[i]; break;
            case NA * NC:       idx = (const int*)d_in[i];   break;
            default: break;
        }
    }

    prep_w2<<<(NA * 256 * 128 + 255) / 256, 256>>>(W2);
    prep_w3<<<(NA * 200 * 256 + 255) / 256, 256>>>(W3);

    cudaFuncSetAttribute(main_kernel,
                         cudaFuncAttributeMaxDynamicSharedMemorySize, SMEM_REQ);
    dim3 grid(NTOK / TM, NA);
    main_kernel<<<grid, 256, SMEM_REQ>>>(x, W1, b1, b2, b3, idx, (float*)d_out);
}

// round 10
// speedup vs baseline: 7.1399x; 1.0227x over previous
#include <cuda_runtime.h>
#include <cuda_fp16.h>
#include <cstdint>
#include <cstddef>

// MultiDecoder: A=10 MLPs 12->128->256->200 over 32768 tokens.
// fp32 scalar layer1 + single-pass fp16 mma.sync (m16n8k16) layers 2 & 3.
// R9: issue-density fixes -- B ldsm_x4 (2 n-tiles/op), 3-stage B pipeline with
// ONE barrier per chunk (prefetch depth 2), fused prep kernel.
// CTA = (articulator, 64 tokens), 8 warps = (2 m-halves) x (4 contiguous n-blocks).

#define NA 10
#define NC 12
#define NH2 128
#define NH 256
#define NF 200
#define NL 120
#define NTOK 32768
#define TM 64

// smem layout (bytes):
//   A plane:  [64 rows][512B, 16B-XOR swizzle]   = 32768  @ 0
//   B stages: 3 x [256 n][80B pitch, 32 k fp16]  = 61440  @ 32768/53248/73728
//   s_w1:     12*128 floats                      = 6144   @ 94208
#define OFF_BST 32768
#define BSTAGE 20480
#define OFF_W1 94208
#define SMEM_REQ 100352

#define ASWZ(row, byte) ((unsigned)(byte) ^ (((unsigned)(row) & 7u) << 4))

// weights fp16, pre-transposed to [n][k]
__device__ __align__(16) __half g_w2t[NA * 256 * 128];  // [a][n=256][k=128]
__device__ __align__(16) __half g_w3t[NA * 200 * 256];  // [a][n=200][k=256]

// ---------------- PTX helpers (base-target only) ----------------
__device__ __forceinline__ void mma_f16(float* c, const unsigned* a, const unsigned* b) {
    asm volatile("mma.sync.aligned.m16n8k16.row.col.f32.f16.f16.f32 "
                 "{%0,%1,%2,%3}, {%4,%5,%6,%7}, {%8,%9}, {%0,%1,%2,%3};"
                 : "+f"(c[0]), "+f"(c[1]), "+f"(c[2]), "+f"(c[3])
                 : "r"(a[0]), "r"(a[1]), "r"(a[2]), "r"(a[3]), "r"(b[0]), "r"(b[1]));
}
__device__ __forceinline__ void ldsm_x4(unsigned* r, uint32_t addr) {
    asm volatile("ldmatrix.sync.aligned.m8n8.x4.shared.b16 {%0,%1,%2,%3}, [%4];"
                 : "=r"(r[0]), "=r"(r[1]), "=r"(r[2]), "=r"(r[3]) : "r"(addr));
}
__device__ __forceinline__ void ldsm_x2(unsigned* r, uint32_t addr) {
    asm volatile("ldmatrix.sync.aligned.m8n8.x2.shared.b16 {%0,%1}, [%2];"
                 : "=r"(r[0]), "=r"(r[1]) : "r"(addr));
}
__device__ __forceinline__ void cpa16(uint32_t dst, const void* src) {
    asm volatile("cp.async.cg.shared.global [%0], [%1], 16;" ::"r"(dst), "l"(src) : "memory");
}
#define CP_COMMIT() asm volatile("cp.async.commit_group;" ::: "memory")
#define CP_WAIT1()  asm volatile("cp.async.wait_group 1;" ::: "memory")
#define CP_WAIT0()  asm volatile("cp.async.wait_group 0;" ::: "memory")

__device__ __forceinline__ uint32_t pack2h(float lo_f, float hi_f) {
    uint32_t r;
    asm("cvt.rn.f16x2.f32 %0, %1, %2;" : "=r"(r) : "f"(hi_f), "f"(lo_f));
    return r;
}

// ---------------- fused prep kernel: fp16 convert + transpose ----------------
#define N_W2 (NA * 256 * 128)
#define N_W3 (NA * 200 * 256)
__global__ void prep_w(const float* __restrict__ W2, const float* __restrict__ W3) {
    int i = blockIdx.x * 256 + threadIdx.x;
    if (i < N_W2) {
        int k = i & 127, n = (i >> 7) & 255, a = i >> 15;
        g_w2t[((size_t)a * 256 + n) * 128 + k] =
            __float2half_rn(W2[((size_t)a * NH2 + k) * NH + n]);
    } else if (i < N_W2 + N_W3) {
        int j = i - N_W2;
        int k = j & 255, n = (j >> 8) % 200, a = j / (200 * 256);
        g_w3t[((size_t)a * 200 + n) * 256 + k] =
            __float2half_rn(W3[((size_t)a * NH + k) * NF + n]);
    }
}

// ---------------- B tile loader: k-chunk of 32, one commit group ----------------
__device__ __forceinline__ void load_btile(uint32_t dstU, const __half* src,
                                           int Kst, int rows, int tid) {
#pragma unroll
    for (int it = 0; it < 4; it++) {
        int i = tid + it * 256;
        if (i < rows * 4) {
            int r = i >> 2, seg = i & 3;
            cpa16(dstU + (unsigned)(r * 80 + seg * 16), src + (size_t)r * Kst + seg * 8);
        }
    }
    CP_COMMIT();
}

// ---------------- one k=32 chunk; B via ldsm_x4 (2 n-tiles per op) ----------------
// LAYER=2: warp ng covers 8 contiguous n-tiles (base ng*8).
// LAYER=3: warp ng covers 7 (ng<3) or 4 (ng==3) tiles (base ng*7).
template <int LAYER>
__device__ __forceinline__ void gemm_chunk(float (&c)[2][8][4], uint32_t su,
                                           uint32_t bBuf, int kc, int lane,
                                           int mrow0, int ng) {
    const int cnt = (LAYER == 2) ? 8 : ((ng < 3) ? 7 : 4);
    const int base = (LAYER == 2) ? ng * 8 : ng * 7;
#pragma unroll
    for (int ks = 0; ks < 2; ks++) {
        const int k0 = kc + ks * 16;
        unsigned af[2][4];
#pragma unroll
        for (int i = 0; i < 2; i++) {
            int row = mrow0 + i * 16 + (lane & 15);
            ldsm_x4(af[i], su + (unsigned)(row * 512) +
                               ASWZ(row, (k0 + ((lane >> 4) << 3)) * 2));
        }
#pragma unroll
        for (int jp = 0; jp < 4; jp++) {
            const int j0 = jp * 2;
            if (LAYER == 2 || j0 + 1 < cnt) {          // x4: tiles tn0, tn0+1
                int tn0 = base + j0;
                unsigned bf[4];
                ldsm_x4(bf, bBuf + (unsigned)((tn0 * 8 + (lane & 7) +
                                               ((lane >> 4) << 3)) * 80 +
                                              ks * 32 + (((lane >> 3) & 1) << 4)));
                mma_f16(c[0][j0], af[0], bf);
                mma_f16(c[1][j0], af[1], bf);
                mma_f16(c[0][j0 + 1], af[0], bf + 2);
                mma_f16(c[1][j0 + 1], af[1], bf + 2);
            } else if (j0 < cnt) {                     // x2 tail: single tile
                int tn = base + j0;
                unsigned bf[2];
                ldsm_x2(bf, bBuf + (unsigned)((tn * 8 + (lane & 7)) * 80 +
                                              ks * 32 + (((lane >> 3) & 1) << 4)));
                mma_f16(c[0][j0], af[0], bf);
                mma_f16(c[1][j0], af[1], bf);
            }
        }
    }
}

// ---------------- main kernel ----------------
__global__ void __launch_bounds__(256, 2)
main_kernel(const float* __restrict__ x, const float* __restrict__ W1,
            const float* __restrict__ b1, const float* __restrict__ b2,
            const float* __restrict__ b3, const int* __restrict__ idx,
            float* __restrict__ out) {
    extern __shared__ char smem[];
    const uint32_t su = (uint32_t)__cvta_generic_to_shared(smem);

    const int a = blockIdx.y;
    const int n0 = blockIdx.x * TM;
    const int tid = threadIdx.x;
    const int wid = tid >> 5;
    const int lane = tid & 31;
    const int mrow0 = (wid & 1) * 32;
    const int ng = wid >> 1;
    const int g = lane >> 2, tg = lane & 3;

    const __half* w2a = g_w2t + (size_t)a * 256 * 128;
    const __half* w3a = g_w3t + (size_t)a * 200 * 256;

    // ---- prologue: chunks q=0,1 (layer2) into stages 0,1 ----
    load_btile(su + OFF_BST, w2a, 128, 256, tid);
    load_btile(su + OFF_BST + BSTAGE, w2a + 32, 128, 256, tid);

    // ---- stage W1 ----
    float* s_w1 = (float*)(smem + OFF_W1);   // [12][128]
    for (int i = tid; i < NC * NH2; i += 256) s_w1[i] = W1[a * NC * NH2 + i];
    __syncthreads();

    // ---- layer 1 (fp32 scalar): h1 = relu(xg@W1+b1) -> A plane (fp16) ----
    {
        const int t = tid & 63;
        const int hb = (tid >> 6) * 32;
        const int* idxa = idx + a * NC;
        float xv[NC];
#pragma unroll
        for (int c = 0; c < NC; c++)
            xv[c] = __ldg(&x[(size_t)(n0 + t) * NL + __ldg(&idxa[c])]);
        float acc[32];
#pragma unroll
        for (int j = 0; j < 32; j++) acc[j] = __ldg(&b1[a * NH2 + hb + j]);
#pragma unroll
        for (int c = 0; c < NC; c++) {
            const float4* wr = (const float4*)(s_w1 + c * NH2 + hb);
#pragma unroll
            for (int q = 0; q < 8; q++) {
                float4 w = wr[q];
                acc[q * 4 + 0] = fmaf(xv[c], w.x, acc[q * 4 + 0]);
                acc[q * 4 + 1] = fmaf(xv[c], w.y, acc[q * 4 + 1]);
                acc[q * 4 + 2] = fmaf(xv[c], w.z, acc[q * 4 + 2]);
                acc[q * 4 + 3] = fmaf(xv[c], w.w, acc[q * 4 + 3]);
            }
        }
        char* rowp = smem + (size_t)t * 512;
#pragma unroll
        for (int q = 0; q < 16; q++) {
            float v0 = fmaxf(acc[2 * q], 0.0f), v1 = fmaxf(acc[2 * q + 1], 0.0f);
            *(uint32_t*)(rowp + ASWZ(t, hb * 2 + q * 4)) = pack2h(v0, v1);
        }
    }

    float cacc[2][8][4];
#pragma unroll
    for (int i = 0; i < 2; i++)
#pragma unroll
        for (int j = 0; j < 8; j++)
#pragma unroll
            for (int q = 0; q < 4; q++) cacc[i][j][q] = 0.0f;

    // ---- layer 2: 4 k-chunks (global q=0..3), stage q%3, prefetch q+2 ----
    for (int c = 0; c < 4; c++) {
        CP_WAIT1();               // chunk c resident
        __syncthreads();          // + stage (c+2)%3 fully consumed (chunk c-1 done)
        int nx = c + 2;
        uint32_t st = su + OFF_BST + ((c + 2) % 3) * BSTAGE;
        if (nx < 4) load_btile(st, w2a + (size_t)nx * 32, 128, 256, tid);
        else        load_btile(st, w3a + (size_t)(nx - 4) * 32, 256, 200, tid);
        gemm_chunk<2>(cacc, su, su + OFF_BST + (c % 3) * BSTAGE, c * 32,
                      lane, mrow0, ng);
    }

    // ---- epilogue 2: bias+relu -> A3 plane (overwrites A2, fp16) ----
    __syncthreads();              // all warps done reading A for layer2
    {
#pragma unroll
        for (int i = 0; i < 2; i++) {
#pragma unroll
            for (int j = 0; j < 8; j++) {
                int col = (ng * 8 + j) * 8 + tg * 2;
                float bb0 = __ldg(&b2[a * NH + col]);
                float bb1 = __ldg(&b2[a * NH + col + 1]);
                int r0 = mrow0 + i * 16 + g;
#pragma unroll
                for (int half = 0; half < 2; half++) {
                    int r = r0 + half * 8;
                    float v0 = fmaxf(cacc[i][j][2 * half + 0] + bb0, 0.0f);
                    float v1 = fmaxf(cacc[i][j][2 * half + 1] + bb1, 0.0f);
                    *(uint32_t*)(smem + (size_t)r * 512 + ASWZ(r, col * 2)) =
                        pack2h(v0, v1);
                }
            }
        }
    }
    __syncthreads();              // A3 visible before layer3 reads

#pragma unroll
    for (int i = 0; i < 2; i++)
#pragma unroll
        for (int j = 0; j < 8; j++)
#pragma unroll
            for (int q = 0; q < 4; q++) cacc[i][j][q] = 0.0f;

    // ---- layer 3: 8 k-chunks (global q=c+4), stage (c+4)%3, prefetch q+2 ----
    for (int c = 0; c < 8; c++) {
        if (c < 7) CP_WAIT1(); else CP_WAIT0();
        __syncthreads();
        int nx = c + 2;
        if (nx < 8)
            load_btile(su + OFF_BST + ((c + 6) % 3) * BSTAGE,
                       w3a + (size_t)nx * 32, 256, 200, tid);
        gemm_chunk<3>(cacc, su, su + OFF_BST + ((c + 4) % 3) * BSTAGE, c * 32,
                      lane, mrow0, ng);
    }

    // ---- epilogue 3: bias add, store fragments directly (f32 out) ----
    {
        const int cnt = (ng < 3) ? 7 : 4;
#pragma unroll
        for (int i = 0; i < 2; i++) {
#pragma unroll
            for (int j = 0; j < 7; j++) {
                if (j < cnt) {
                    int col = (ng * 7 + j) * 8 + tg * 2;
                    float bb0 = __ldg(&b3[a * NF + col]);
                    float bb1 = __ldg(&b3[a * NF + col + 1]);
                    int r0 = mrow0 + i * 16 + g;
#pragma unroll
                    for (int half = 0; half < 2; half++) {
                        int r = r0 + half * 8;
                        float2 v = make_float2(cacc[i][j][2 * half + 0] + bb0,
                                               cacc[i][j][2 * half + 1] + bb1);
                        *(float2*)&out[((size_t)(n0 + r) * NA + a) * NF + col] = v;
                    }
                }
            }
        }
    }
}

// ---------------- launch ----------------
extern "C" void kernel_launch(void* const* d_in, const int* in_sizes, int n_in,
                              void* d_out, int out_size) {
    const float *x = nullptr, *W1 = nullptr, *b1 = nullptr, *W2 = nullptr,
                *b2 = nullptr, *W3 = nullptr, *b3 = nullptr;
    const int* idx = nullptr;
    for (int i = 0; i < n_in; i++) {
        switch (in_sizes[i]) {
            case NTOK * NL:     x   = (const float*)d_in[i]; break;
            case NA * NC * NH2: W1  = (const float*)d_in[i]; break;
            case NA * NH2:      b1  = (const float*)d_in[i]; break;
            case NA * NH2 * NH: W2  = (const float*)d_in[i]; break;
            case NA * NH:       b2  = (const float*)d_in[i]; break;
            case NA * NH * NF:  W3  = (const float*)d_in[i]; break;
            case NA * NF:       b3  = (const float*)d_in[i]; break;
            case NA * NC:       idx = (const int*)d_in[i];   break;
            default: break;
        }
    }

    prep_w<<<(N_W2 + N_W3 + 255) / 256, 256>>>(W2, W3);

    cudaFuncSetAttribute(main_kernel,
                         cudaFuncAttributeMaxDynamicSharedMemorySize, SMEM_REQ);
    dim3 grid(NTOK / TM, NA);
    main_kernel<<<grid, 256, SMEM_REQ>>>(x, W1, b1, b2, b3, idx, (float*)d_out);
}

// round 11
// speedup vs baseline: 7.2444x; 1.0146x over previous
#include <cuda_runtime.h>
#include <cuda_fp16.h>
#include <cstdint>
#include <cstddef>

// MultiDecoder: A=10 MLPs 12->128->256->200 over 32768 tokens.
// fp32 scalar layer1 + single-pass fp16 mma.sync (m16n8k16) layers 2 & 3.
// R11: latency-bound fix -- batch all ldsm per k-step (MLP 6) before MMAs,
// non-volatile mma so ptxas schedules MMAs into the next load shadow.
// CTA = (articulator, 64 tokens), 8 warps, 2 CTAs/SM.

#define NA 10
#define NC 12
#define NH2 128
#define NH 256
#define NF 200
#define NL 120
#define NTOK 32768
#define TM 64

// smem layout (bytes):
//   A plane:  [64 rows][512B, 16B-XOR swizzle]   = 32768  @ 0
//   B stages: 3 x [256 n][80B pitch, 32 k fp16]  = 61440  @ 32768/53248/73728
//   s_w1:     12*128 floats                      = 6144   @ 94208
#define OFF_BST 32768
#define BSTAGE 20480
#define OFF_W1 94208
#define SMEM_REQ 100352

#define ASWZ(row, byte) ((unsigned)(byte) ^ (((unsigned)(row) & 7u) << 4))

// weights fp16, pre-transposed to [n][k]
__device__ __align__(16) __half g_w2t[NA * 256 * 128];  // [a][n=256][k=128]
__device__ __align__(16) __half g_w3t[NA * 200 * 256];  // [a][n=200][k=256]

// ---------------- PTX helpers (base-target only) ----------------
// NOTE: mma is NOT volatile -- pure register in/out, lets ptxas schedule.
__device__ __forceinline__ void mma_f16(float* c, const unsigned* a, const unsigned* b) {
    asm("mma.sync.aligned.m16n8k16.row.col.f32.f16.f16.f32 "
        "{%0,%1,%2,%3}, {%4,%5,%6,%7}, {%8,%9}, {%0,%1,%2,%3};"
        : "+f"(c[0]), "+f"(c[1]), "+f"(c[2]), "+f"(c[3])
        : "r"(a[0]), "r"(a[1]), "r"(a[2]), "r"(a[3]), "r"(b[0]), "r"(b[1]));
}
__device__ __forceinline__ void ldsm_x4(unsigned* r, uint32_t addr) {
    asm volatile("ldmatrix.sync.aligned.m8n8.x4.shared.b16 {%0,%1,%2,%3}, [%4];"
                 : "=r"(r[0]), "=r"(r[1]), "=r"(r[2]), "=r"(r[3]) : "r"(addr));
}
__device__ __forceinline__ void ldsm_x2(unsigned* r, uint32_t addr) {
    asm volatile("ldmatrix.sync.aligned.m8n8.x2.shared.b16 {%0,%1}, [%2];"
                 : "=r"(r[0]), "=r"(r[1]) : "r"(addr));
}
__device__ __forceinline__ void cpa16(uint32_t dst, const void* src) {
    asm volatile("cp.async.cg.shared.global [%0], [%1], 16;" ::"r"(dst), "l"(src) : "memory");
}
#define CP_COMMIT() asm volatile("cp.async.commit_group;" ::: "memory")
#define CP_WAIT1()  asm volatile("cp.async.wait_group 1;" ::: "memory")
#define CP_WAIT0()  asm volatile("cp.async.wait_group 0;" ::: "memory")

__device__ __forceinline__ uint32_t pack2h(float lo_f, float hi_f) {
    uint32_t r;
    asm("cvt.rn.f16x2.f32 %0, %1, %2;" : "=r"(r) : "f"(hi_f), "f"(lo_f));
    return r;
}

// ---------------- fused prep kernel: fp16 convert + transpose ----------------
#define N_W2 (NA * 256 * 128)
#define N_W3 (NA * 200 * 256)
__global__ void prep_w(const float* __restrict__ W2, const float* __restrict__ W3) {
    int i = blockIdx.x * 256 + threadIdx.x;
    if (i < N_W2) {
        int k = i & 127, n = (i >> 7) & 255, a = i >> 15;
        g_w2t[((size_t)a * 256 + n) * 128 + k] =
            __float2half_rn(W2[((size_t)a * NH2 + k) * NH + n]);
    } else if (i < N_W2 + N_W3) {
        int j = i - N_W2;
        int k = j & 255, n = (j >> 8) % 200, a = j / (200 * 256);
        g_w3t[((size_t)a * 200 + n) * 256 + k] =
            __float2half_rn(W3[((size_t)a * NH + k) * NF + n]);
    }
}

// ---------------- B tile loader: k-chunk of 32, one commit group ----------------
__device__ __forceinline__ void load_btile(uint32_t dstU, const __half* src,
                                           int Kst, int rows, int tid) {
#pragma unroll
    for (int it = 0; it < 4; it++) {
        int i = tid + it * 256;
        if (i < rows * 4) {
            int r = i >> 2, seg = i & 3;
            cpa16(dstU + (unsigned)(r * 80 + seg * 16), src + (size_t)r * Kst + seg * 8);
        }
    }
    CP_COMMIT();
}

// ---------------- one k=32 chunk: batch loads, then MMAs ----------------
// LAYER=2: warp ng covers 8 contiguous n-tiles (base ng*8): 4 x4 B-loads.
// LAYER=3: ng<3: 7 tiles (3 x4 + 1 x2); ng==3: 4 tiles (2 x4). base ng*7.
template <int LAYER>
__device__ __forceinline__ void gemm_chunk(float (&c)[2][8][4], uint32_t su,
                                           uint32_t bBuf, int kc, int lane,
                                           int mrow0, int ng) {
    const int base = (LAYER == 2) ? ng * 8 : ng * 7;
    const int npairs = (LAYER == 2) ? 4 : ((ng < 3) ? 3 : 2);
    const bool tail = (LAYER == 3) && (ng < 3);
#pragma unroll
    for (int ks = 0; ks < 2; ks++) {
        const int k0 = kc + ks * 16;
        // ---- batch ALL fragment loads (MLP = 2 + npairs [+1]) ----
        unsigned af[2][4];
#pragma unroll
        for (int i = 0; i < 2; i++) {
            int row = mrow0 + i * 16 + (lane & 15);
            ldsm_x4(af[i], su + (unsigned)(row * 512) +
                               ASWZ(row, (k0 + ((lane >> 4) << 3)) * 2));
        }
        unsigned bf[16];
#pragma unroll
        for (int jp = 0; jp < 4; jp++) {
            if (jp < npairs) {
                int tn0 = base + jp * 2;
                ldsm_x4(bf + 4 * jp, bBuf + (unsigned)((tn0 * 8 + (lane & 7) +
                                                        ((lane >> 4) << 3)) * 80 +
                                                       ks * 32 + (((lane >> 3) & 1) << 4)));
            }
        }
        if (tail) {
            int tn = base + 6;
            ldsm_x2(bf + 12, bBuf + (unsigned)((tn * 8 + (lane & 7)) * 80 +
                                               ks * 32 + (((lane >> 3) & 1) << 4)));
        }
        // ---- MMAs (non-volatile: ptxas may interleave/sink) ----
#pragma unroll
        for (int jp = 0; jp < 4; jp++) {
            if (jp < npairs) {
                const int j0 = jp * 2;
                mma_f16(c[0][j0], af[0], bf + 4 * jp);
                mma_f16(c[1][j0], af[1], bf + 4 * jp);
                mma_f16(c[0][j0 + 1], af[0], bf + 4 * jp + 2);
                mma_f16(c[1][j0 + 1], af[1], bf + 4 * jp + 2);
            }
        }
        if (tail) {
            mma_f16(c[0][6], af[0], bf + 12);
            mma_f16(c[1][6], af[1], bf + 12);
        }
    }
}

// ---------------- main kernel ----------------
__global__ void __launch_bounds__(256, 2)
main_kernel(const float* __restrict__ x, const float* __restrict__ W1,
            const float* __restrict__ b1, const float* __restrict__ b2,
            const float* __restrict__ b3, const int* __restrict__ idx,
            float* __restrict__ out) {
    extern __shared__ char smem[];
    const uint32_t su = (uint32_t)__cvta_generic_to_shared(smem);

    const int a = blockIdx.y;
    const int n0 = blockIdx.x * TM;
    const int tid = threadIdx.x;
    const int wid = tid >> 5;
    const int lane = tid & 31;
    const int mrow0 = (wid & 1) * 32;
    const int ng = wid >> 1;
    const int g = lane >> 2, tg = lane & 3;

    const __half* w2a = g_w2t + (size_t)a * 256 * 128;
    const __half* w3a = g_w3t + (size_t)a * 200 * 256;

    // ---- prologue: chunks q=0,1 (layer2) into stages 0,1 ----
    load_btile(su + OFF_BST, w2a, 128, 256, tid);
    load_btile(su + OFF_BST + BSTAGE, w2a + 32, 128, 256, tid);

    // ---- stage W1 ----
    float* s_w1 = (float*)(smem + OFF_W1);   // [12][128]
    for (int i = tid; i < NC * NH2; i += 256) s_w1[i] = W1[a * NC * NH2 + i];
    __syncthreads();

    // ---- layer 1 (fp32 scalar): h1 = relu(xg@W1+b1) -> A plane (fp16) ----
    {
        const int t = tid & 63;
        const int hb = (tid >> 6) * 32;
        const int* idxa = idx + a * NC;
        float xv[NC];
#pragma unroll
        for (int c = 0; c < NC; c++)
            xv[c] = __ldg(&x[(size_t)(n0 + t) * NL + __ldg(&idxa[c])]);
        float acc[32];
#pragma unroll
        for (int j = 0; j < 32; j++) acc[j] = __ldg(&b1[a * NH2 + hb + j]);
#pragma unroll
        for (int c = 0; c < NC; c++) {
            const float4* wr = (const float4*)(s_w1 + c * NH2 + hb);
#pragma unroll
            for (int q = 0; q < 8; q++) {
                float4 w = wr[q];
                acc[q * 4 + 0] = fmaf(xv[c], w.x, acc[q * 4 + 0]);
                acc[q * 4 + 1] = fmaf(xv[c], w.y, acc[q * 4 + 1]);
                acc[q * 4 + 2] = fmaf(xv[c], w.z, acc[q * 4 + 2]);
                acc[q * 4 + 3] = fmaf(xv[c], w.w, acc[q * 4 + 3]);
            }
        }
        char* rowp = smem + (size_t)t * 512;
#pragma unroll
        for (int q = 0; q < 16; q++) {
            float v0 = fmaxf(acc[2 * q], 0.0f), v1 = fmaxf(acc[2 * q + 1], 0.0f);
            *(uint32_t*)(rowp + ASWZ(t, hb * 2 + q * 4)) = pack2h(v0, v1);
        }
    }

    float cacc[2][8][4];
#pragma unroll
    for (int i = 0; i < 2; i++)
#pragma unroll
        for (int j = 0; j < 8; j++)
#pragma unroll
            for (int q = 0; q < 4; q++) cacc[i][j][q] = 0.0f;

    // ---- layer 2: 4 k-chunks (global q=0..3), stage q%3, prefetch q+2 ----
    for (int c = 0; c < 4; c++) {
        CP_WAIT1();               // chunk c resident
        __syncthreads();          // + stage (c+2)%3 fully consumed
        int nx = c + 2;
        uint32_t st = su + OFF_BST + ((c + 2) % 3) * BSTAGE;
        if (nx < 4) load_btile(st, w2a + (size_t)nx * 32, 128, 256, tid);
        else        load_btile(st, w3a + (size_t)(nx - 4) * 32, 256, 200, tid);
        gemm_chunk<2>(cacc, su, su + OFF_BST + (c % 3) * BSTAGE, c * 32,
                      lane, mrow0, ng);
    }

    // ---- epilogue 2: bias+relu -> A3 plane (overwrites A2, fp16) ----
    __syncthreads();              // all warps done reading A for layer2
    {
#pragma unroll
        for (int i = 0; i < 2; i++) {
#pragma unroll
            for (int j = 0; j < 8; j++) {
                int col = (ng * 8 + j) * 8 + tg * 2;
                float bb0 = __ldg(&b2[a * NH + col]);
                float bb1 = __ldg(&b2[a * NH + col + 1]);
                int r0 = mrow0 + i * 16 + g;
#pragma unroll
                for (int half = 0; half < 2; half++) {
                    int r = r0 + half * 8;
                    float v0 = fmaxf(cacc[i][j][2 * half + 0] + bb0, 0.0f);
                    float v1 = fmaxf(cacc[i][j][2 * half + 1] + bb1, 0.0f);
                    *(uint32_t*)(smem + (size_t)r * 512 + ASWZ(r, col * 2)) =
                        pack2h(v0, v1);
                }
            }
        }
    }
    __syncthreads();              // A3 visible before layer3 reads

#pragma unroll
    for (int i = 0; i < 2; i++)
#pragma unroll
        for (int j = 0; j < 8; j++)
#pragma unroll
            for (int q = 0; q < 4; q++) cacc[i][j][q] = 0.0f;

    // ---- layer 3: 8 k-chunks (global q=c+4), stage (c+4)%3, prefetch q+2 ----
    for (int c = 0; c < 8; c++) {
        if (c < 7) CP_WAIT1(); else CP_WAIT0();
        __syncthreads();
        int nx = c + 2;
        if (nx < 8)
            load_btile(su + OFF_BST + ((c + 6) % 3) * BSTAGE,
                       w3a + (size_t)nx * 32, 256, 200, tid);
        gemm_chunk<3>(cacc, su, su + OFF_BST + ((c + 4) % 3) * BSTAGE, c * 32,
                      lane, mrow0, ng);
    }

    // ---- epilogue 3: bias add, store fragments directly (f32 out) ----
    {
        const int cnt = (ng < 3) ? 7 : 4;
#pragma unroll
        for (int i = 0; i < 2; i++) {
#pragma unroll
            for (int j = 0; j < 7; j++) {
                if (j < cnt) {
                    int col = (ng * 7 + j) * 8 + tg * 2;
                    float bb0 = __ldg(&b3[a * NF + col]);
                    float bb1 = __ldg(&b3[a * NF + col + 1]);
                    int r0 = mrow0 + i * 16 + g;
#pragma unroll
                    for (int half = 0; half < 2; half++) {
                        int r = r0 + half * 8;
                        float2 v = make_float2(cacc[i][j][2 * half + 0] + bb0,
                                               cacc[i][j][2 * half + 1] + bb1);
                        *(float2*)&out[((size_t)(n0 + r) * NA + a) * NF + col] = v;
                    }
                }
            }
        }
    }
}

// ---------------- launch ----------------
extern "C" void kernel_launch(void* const* d_in, const int* in_sizes, int n_in,
                              void* d_out, int out_size) {
    const float *x = nullptr, *W1 = nullptr, *b1 = nullptr, *W2 = nullptr,
                *b2 = nullptr, *W3 = nullptr, *b3 = nullptr;
    const int* idx = nullptr;
    for (int i = 0; i < n_in; i++) {
        switch (in_sizes[i]) {
            case NTOK * NL:     x   = (const float*)d_in[i]; break;
            case NA * NC * NH2: W1  = (const float*)d_in[i]; break;
            case NA * NH2:      b1  = (const float*)d_in[i]; break;
            case NA * NH2 * NH: W2  = (const float*)d_in[i]; break;
            case NA * NH:       b2  = (const float*)d_in[i]; break;
            case NA * NH * NF:  W3  = (const float*)d_in[i]; break;
            case NA * NF:       b3  = (const float*)d_in[i]; break;
            case NA * NC:       idx = (const int*)d_in[i];   break;
            default: break;
        }
    }

    prep_w<<<(N_W2 + N_W3 + 255) / 256, 256>>>(W2, W3);

    cudaFuncSetAttribute(main_kernel,
                         cudaFuncAttributeMaxDynamicSharedMemorySize, SMEM_REQ);
    dim3 grid(NTOK / TM, NA);
    main_kernel<<<grid, 256, SMEM_REQ>>>(x, W1, b1, b2, b3, idx, (float*)d_out);
}

// round 14
// speedup vs baseline: 8.2987x; 1.1455x over previous
#include <cuda_runtime.h>
#include <cuda_fp16.h>
#include <cstdint>
#include <cstddef>

// MultiDecoder: A=10 MLPs 12->128->256->200 over 32768 tokens.
// fp32 scalar layer1 + single-pass fp16 mma.sync (m16n8k16) layers 2 & 3.
// R13: warp-private B pipelines (R12) with FIXED stage indexing: prefetch
// depth 2 (not 3) so the in-loop load targets stage (q+2)%3, never the stage
// being read (q%3). No barriers inside GEMM loops; 4 at layer boundaries.
// CTA = (articulator, 64 tokens), 8 warps, 2 CTAs/SM.

#define NA 10
#define NC 12
#define NH2 128
#define NH 256
#define NF 200
#define NL 120
#define NTOK 32768
#define TM 64

// smem layout (bytes):
//   A plane:  [64 rows][512B, 16B-XOR swizzle]        = 32768  @ 0
//   B stages: [3 stages][8 warps][32 rows][80B pitch] = 61440  @ 32768
//   s_w1:     12*128 floats                           = 6144   @ 94208
#define OFF_BST 32768
#define BWSLOT 2560                    // 32 rows * 80B, per warp per stage
#define BSTAGE (8 * BWSLOT)            // 20480
#define OFF_W1 94208
#define SMEM_REQ 100352

#define ASWZ(row, byte) ((unsigned)(byte) ^ (((unsigned)(row) & 7u) << 4))

// weights fp16, pre-transposed to [n][k]
__device__ __align__(16) __half g_w2t[NA * 256 * 128];  // [a][n=256][k=128]
__device__ __align__(16) __half g_w3t[NA * 200 * 256];  // [a][n=200][k=256]

// ---------------- PTX helpers (base-target only) ----------------
__device__ __forceinline__ void mma_f16(float* c, const unsigned* a, const unsigned* b) {
    asm("mma.sync.aligned.m16n8k16.row.col.f32.f16.f16.f32 "
        "{%0,%1,%2,%3}, {%4,%5,%6,%7}, {%8,%9}, {%0,%1,%2,%3};"
        : "+f"(c[0]), "+f"(c[1]), "+f"(c[2]), "+f"(c[3])
        : "r"(a[0]), "r"(a[1]), "r"(a[2]), "r"(a[3]), "r"(b[0]), "r"(b[1]));
}
__device__ __forceinline__ void ldsm_x4(unsigned* r, uint32_t addr) {
    asm volatile("ldmatrix.sync.aligned.m8n8.x4.shared.b16 {%0,%1,%2,%3}, [%4];"
                 : "=r"(r[0]), "=r"(r[1]), "=r"(r[2]), "=r"(r[3]) : "r"(addr));
}
__device__ __forceinline__ void ldsm_x2(unsigned* r, uint32_t addr) {
    asm volatile("ldmatrix.sync.aligned.m8n8.x2.shared.b16 {%0,%1}, [%2];"
                 : "=r"(r[0]), "=r"(r[1]) : "r"(addr));
}
__device__ __forceinline__ void cpa16(uint32_t dst, const void* src) {
    asm volatile("cp.async.cg.shared.global [%0], [%1], 16;" ::"r"(dst), "l"(src) : "memory");
}
#define CP_COMMIT() asm volatile("cp.async.commit_group;" ::: "memory")
#define CP_WAITN(n) asm volatile("cp.async.wait_group %0;" ::"n"(n) : "memory")

__device__ __forceinline__ uint32_t pack2h(float lo_f, float hi_f) {
    uint32_t r;
    asm("cvt.rn.f16x2.f32 %0, %1, %2;" : "=r"(r) : "f"(hi_f), "f"(lo_f));
    return r;
}

// ---------------- fused prep kernel: fp16 convert + transpose ----------------
#define N_W2 (NA * 256 * 128)
#define N_W3 (NA * 200 * 256)
__global__ void prep_w(const float* __restrict__ W2, const float* __restrict__ W3) {
    int i = blockIdx.x * 256 + threadIdx.x;
    if (i < N_W2) {
        int k = i & 127, n = (i >> 7) & 255, a = i >> 15;
        g_w2t[((size_t)a * 256 + n) * 128 + k] =
            __float2half_rn(W2[((size_t)a * NH2 + k) * NH + n]);
    } else if (i < N_W2 + N_W3) {
        int j = i - N_W2;
        int k = j & 255, n = (j >> 8) % 200, a = j / (200 * 256);
        g_w3t[((size_t)a * 200 + n) * 256 + k] =
            __float2half_rn(W3[((size_t)a * NH + k) * NF + n]);
    }
}

// ---------------- warp-private B slice loader (32 lanes, own commit group) ----
__device__ __forceinline__ void warp_load_b(uint32_t dstU, const __half* src,
                                            int Kst, int rows, int lane) {
#pragma unroll
    for (int it = 0; it < 4; it++) {
        int i = it * 32 + lane;
        if (i < rows * 4) {
            int r = i >> 2, seg = i & 3;
            cpa16(dstU + (unsigned)(r * 80 + seg * 16), src + (size_t)r * Kst + seg * 8);
        }
    }
    CP_COMMIT();
}

// ---------------- chunk load dispatch by global chunk id q (0..11) ----------
__device__ __forceinline__ void load_chunk_q(int q, uint32_t bslot0,
                                             const __half* w2w, const __half* w3w,
                                             int rows3, int lane) {
    uint32_t st = bslot0 + (q % 3) * BSTAGE;
    if (q < 4) warp_load_b(st, w2w + (size_t)q * 32, 128, 32, lane);
    else       warp_load_b(st, w3w + (size_t)(q - 4) * 32, 256, rows3, lane);
}

// ---------------- one k=32 chunk over the warp's private slice ----------------
// Warp covers all 64 m-rows (4 m-tiles). NT = n-tiles this warp owns (4, 3).
template <int NT>
__device__ __forceinline__ void gemm_chunk(float (&c)[4][4][4], uint32_t su,
                                           uint32_t bSlot, int kc, int lane) {
#pragma unroll
    for (int ks = 0; ks < 2; ks++) {
        const int k0 = kc + ks * 16;
        unsigned af[4][4];
#pragma unroll
        for (int mt = 0; mt < 4; mt++) {
            int row = mt * 16 + (lane & 15);
            ldsm_x4(af[mt], su + (unsigned)(row * 512) +
                                ASWZ(row, (k0 + ((lane >> 4) << 3)) * 2));
        }
        unsigned bf[8];
        ldsm_x4(bf, bSlot + (unsigned)(((lane & 7) + ((lane >> 4) << 3)) * 80 +
                                       ks * 32 + (((lane >> 3) & 1) << 4)));
        if (NT == 4) {
            ldsm_x4(bf + 4, bSlot + (unsigned)((16 + (lane & 7) + ((lane >> 4) << 3)) * 80 +
                                               ks * 32 + (((lane >> 3) & 1) << 4)));
        } else {  // NT == 3: tiles 0,1 via x4 above; tile 2 via x2
            ldsm_x2(bf + 4, bSlot + (unsigned)((16 + (lane & 7)) * 80 +
                                               ks * 32 + (((lane >> 3) & 1) << 4)));
        }
#pragma unroll
        for (int j = 0; j < NT; j++)
#pragma unroll
            for (int mt = 0; mt < 4; mt++)
                mma_f16(c[mt][j], af[mt], bf + 2 * j);
    }
}

// ---------------- main kernel ----------------
__global__ void __launch_bounds__(256, 2)
main_kernel(const float* __restrict__ x, const float* __restrict__ W1,
            const float* __restrict__ b1, const float* __restrict__ b2,
            const float* __restrict__ b3, const int* __restrict__ idx,
            float* __restrict__ out) {
    extern __shared__ char smem[];
    const uint32_t su = (uint32_t)__cvta_generic_to_shared(smem);

    const int a = blockIdx.y;
    const int n0 = blockIdx.x * TM;
    const int tid = threadIdx.x;
    const int wid = tid >> 5;
    const int lane = tid & 31;
    const int g = lane >> 2, tg = lane & 3;

    // n ownership: layer2 = 32 cols @ wid*32; layer3 = 3 tiles @ wid*3 (wid<7),
    // 4 tiles @ 21 (wid==7).
    const int nb2 = wid * 32;
    const int t3base = (wid < 7) ? wid * 3 : 21;
    const int nt3 = (wid < 7) ? 3 : 4;

    const __half* w2w = g_w2t + (size_t)a * 256 * 128 + (size_t)nb2 * 128;
    const __half* w3w = g_w3t + (size_t)a * 200 * 256 + (size_t)t3base * 8 * 256;
    const int rows3 = nt3 * 8;

    const uint32_t bslot0 = su + OFF_BST + wid * BWSLOT;

    // ---- prologue: prefetch depth 2 -- chunks q=0 (stage0), q=1 (stage1) ----
    load_chunk_q(0, bslot0, w2w, w3w, rows3, lane);
    load_chunk_q(1, bslot0, w2w, w3w, rows3, lane);

    // ---- stage W1 ----
    float* s_w1 = (float*)(smem + OFF_W1);   // [12][128]
    for (int i = tid; i < NC * NH2; i += 256) s_w1[i] = W1[a * NC * NH2 + i];
    __syncthreads();                                       // barrier 1

    // ---- layer 1 (fp32 scalar): h1 = relu(xg@W1+b1) -> A plane (fp16) ----
    {
        const int t = tid & 63;
        const int hb = (tid >> 6) * 32;
        const int* idxa = idx + a * NC;
        float xv[NC];
#pragma unroll
        for (int c = 0; c < NC; c++)
            xv[c] = __ldg(&x[(size_t)(n0 + t) * NL + __ldg(&idxa[c])]);
        float acc[32];
#pragma unroll
        for (int j = 0; j < 32; j++) acc[j] = __ldg(&b1[a * NH2 + hb + j]);
#pragma unroll
        for (int c = 0; c < NC; c++) {
            const float4* wr = (const float4*)(s_w1 + c * NH2 + hb);
#pragma unroll
            for (int q = 0; q < 8; q++) {
                float4 w = wr[q];
                acc[q * 4 + 0] = fmaf(xv[c], w.x, acc[q * 4 + 0]);
                acc[q * 4 + 1] = fmaf(xv[c], w.y, acc[q * 4 + 1]);
                acc[q * 4 + 2] = fmaf(xv[c], w.z, acc[q * 4 + 2]);
                acc[q * 4 + 3] = fmaf(xv[c], w.w, acc[q * 4 + 3]);
            }
        }
        char* rowp = smem + (size_t)t * 512;
#pragma unroll
        for (int q = 0; q < 16; q++) {
            float v0 = fmaxf(acc[2 * q], 0.0f), v1 = fmaxf(acc[2 * q + 1], 0.0f);
            *(uint32_t*)(rowp + ASWZ(t, hb * 2 + q * 4)) = pack2h(v0, v1);
        }
    }
    __syncthreads();                                       // barrier 2: A2 ready

    float cacc[4][4][4];
#pragma unroll
    for (int mt = 0; mt < 4; mt++)
#pragma unroll
        for (int j = 0; j < 4; j++)
#pragma unroll
            for (int q = 0; q < 4; q++) cacc[mt][j][q] = 0.0f;

    // ---- layer 2: chunks q=0..3, warp-private pipeline, NO barriers ----
    // invariant at top of iter q: groups pending = {q, q+1}; wait(1) -> q done;
    // load q+2 into stage (q+2)%3 (distinct from read stage q%3 and (q+1)%3).
    for (int q = 0; q < 4; q++) {
        CP_WAITN(1);
        if (q + 2 < 12) load_chunk_q(q + 2, bslot0, w2w, w3w, rows3, lane);
        gemm_chunk<4>(cacc, su, bslot0 + (q % 3) * BSTAGE, q * 32, lane);
    }

    // ---- epilogue 2: bias+relu -> A3 plane (overwrites A2, fp16) ----
    __syncthreads();                                       // barrier 3: A2 reads done
    {
#pragma unroll
        for (int mt = 0; mt < 4; mt++) {
#pragma unroll
            for (int j = 0; j < 4; j++) {
                int col = nb2 + j * 8 + tg * 2;
                float bb0 = __ldg(&b2[a * NH + col]);
                float bb1 = __ldg(&b2[a * NH + col + 1]);
                int r0 = mt * 16 + g;
#pragma unroll
                for (int half = 0; half < 2; half++) {
                    int r = r0 + half * 8;
                    float v0 = fmaxf(cacc[mt][j][2 * half + 0] + bb0, 0.0f);
                    float v1 = fmaxf(cacc[mt][j][2 * half + 1] + bb1, 0.0f);
                    *(uint32_t*)(smem + (size_t)r * 512 + ASWZ(r, col * 2)) =
                        pack2h(v0, v1);
                }
            }
        }
    }
    __syncthreads();                                       // barrier 4: A3 ready

#pragma unroll
    for (int mt = 0; mt < 4; mt++)
#pragma unroll
        for (int j = 0; j < 4; j++)
#pragma unroll
            for (int q = 0; q < 4; q++) cacc[mt][j][q] = 0.0f;

    // ---- layer 3: chunks q=4..11, warp-private pipeline, NO barriers ----
    for (int q = 4; q < 12; q++) {
        if (q < 10) CP_WAITN(1);
        else if (q == 10) CP_WAITN(1);   // pending {10,11} -> 10 done
        else CP_WAITN(0);                // pending {11}    -> 11 done
        if (q + 2 < 12) load_chunk_q(q + 2, bslot0, w2w, w3w, rows3, lane);
        if (nt3 == 3)
            gemm_chunk<3>(cacc, su, bslot0 + (q % 3) * BSTAGE, (q - 4) * 32, lane);
        else
            gemm_chunk<4>(cacc, su, bslot0 + (q % 3) * BSTAGE, (q - 4) * 32, lane);
    }

    // ---- epilogue 3: bias add, store fragments directly (f32 out) ----
    {
#pragma unroll
        for (int mt = 0; mt < 4; mt++) {
#pragma unroll
            for (int j = 0; j < 4; j++) {
                if (j < nt3) {
                    int col = (t3base + j) * 8 + tg * 2;
                    float bb0 = __ldg(&b3[a * NF + col]);
                    float bb1 = __ldg(&b3[a * NF + col + 1]);
                    int r0 = mt * 16 + g;
#pragma unroll
                    for (int half = 0; half < 2; half++) {
                        int r = r0 + half * 8;
                        float2 v = make_float2(cacc[mt][j][2 * half + 0] + bb0,
                                               cacc[mt][j][2 * half + 1] + bb1);
                        *(float2*)&out[((size_t)(n0 + r) * NA + a) * NF + col] = v;
                    }
                }
            }
        }
    }
}

// ---------------- launch ----------------
extern "C" void kernel_launch(void* const* d_in, const int* in_sizes, int n_in,
                              void* d_out, int out_size) {
    const float *x = nullptr, *W1 = nullptr, *b1 = nullptr, *W2 = nullptr,
                *b2 = nullptr, *W3 = nullptr, *b3 = nullptr;
    const int* idx = nullptr;
    for (int i = 0; i < n_in; i++) {
        switch (in_sizes[i]) {
            case NTOK * NL:     x   = (const float*)d_in[i]; break;
            case NA * NC * NH2: W1  = (const float*)d_in[i]; break;
            case NA * NH2:      b1  = (const float*)d_in[i]; break;
            case NA * NH2 * NH: W2  = (const float*)d_in[i]; break;
            case NA * NH:       b2  = (const float*)d_in[i]; break;
            case NA * NH * NF:  W3  = (const float*)d_in[i]; break;
            case NA * NF:       b3  = (const float*)d_in[i]; break;
            case NA * NC:       idx = (const int*)d_in[i];   break;
            default: break;
        }
    }

    prep_w<<<(N_W2 + N_W3 + 255) / 256, 256>>>(W2, W3);

    cudaFuncSetAttribute(main_kernel,
                         cudaFuncAttributeMaxDynamicSharedMemorySize, SMEM_REQ);
    dim3 grid(NTOK / TM, NA);
    main_kernel<<<grid, 256, SMEM_REQ>>>(x, W1, b1, b2, b3, idx, (float*)d_out);
}